// round 1
// baseline (speedup 1.0000x reference)
#include <cuda_runtime.h>
#include <math.h>

// Problem constants
#define BSZ    2
#define CDIM   256
#define NDIM   16384      // 128*128
#define HDIM   128
#define WDIM   128
#define SRF    4
#define NKV    1024       // 32*32
#define NHEADS 8
#define HD     32
#define EPSBN  1e-5f
#define KSR    4096       // CDIM*SRF*SRF

// ---------------- scratch (device globals; no allocation allowed) ------------
__device__ float g_q   [BSZ * CDIM * NDIM];   // q as (b, o=h*32+d, n)
__device__ float g_xr  [BSZ * CDIM * NKV];    // spatial-reduced + BN
__device__ float g_k   [BSZ * CDIM * NKV];    // k as (b, o=h*32+d, m)
__device__ float g_attn[BSZ * NHEADS * NDIM]; // per-head max
__device__ float g_S   [BSZ * NDIM];          // sum over heads
__device__ float g_v   [BSZ * CDIM];          // mean-pooled x
__device__ float g_alpha[BSZ * CDIM];         // p * gamma/sqrt(var+eps)
__device__ float g_bias [CDIM];               // beta - mean*gamma/sqrt(var+eps)

// ---------------- generic W(OxK) @ X(b,K,Ncol) GEMM --------------------------
// 64x64 tile, BK=16, 256 threads, 4x4 per thread.
__global__ __launch_bounds__(256) void gemm_wx(
    const float* __restrict__ W, const float* __restrict__ X,
    float* __restrict__ Out, int K, int Ncol) {
    __shared__ float As[16][64];  // [k][o]
    __shared__ float Bs[16][64];  // [k][n]
    const int b  = blockIdx.z;
    const float* Xb = X + (size_t)b * K * Ncol;
    float*       Ob = Out + (size_t)b * CDIM * Ncol;
    const int bm = blockIdx.y * 64;
    const int bn = blockIdx.x * 64;
    const int tid = threadIdx.x;
    const int tm = tid >> 4, tn = tid & 15;

    float acc[4][4] = {};
    for (int k0 = 0; k0 < K; k0 += 16) {
        // load A: W[bm+ar][k0+ac .. +3]
        const int ar = tid >> 2, ac = (tid & 3) * 4;
        float4 a4 = *(const float4*)&W[(size_t)(bm + ar) * K + k0 + ac];
        As[ac + 0][ar] = a4.x; As[ac + 1][ar] = a4.y;
        As[ac + 2][ar] = a4.z; As[ac + 3][ar] = a4.w;
        // load B: X[k0+br][bn+bc .. +3]
        const int br = tid >> 4, bc = (tid & 15) * 4;
        *(float4*)&Bs[br][bc] = *(const float4*)&Xb[(size_t)(k0 + br) * Ncol + bn + bc];
        __syncthreads();
        #pragma unroll
        for (int kk = 0; kk < 16; ++kk) {
            float4 av = *(const float4*)&As[kk][tm * 4];
            float4 bv = *(const float4*)&Bs[kk][tn * 4];
            float a[4] = {av.x, av.y, av.z, av.w};
            float bb[4] = {bv.x, bv.y, bv.z, bv.w};
            #pragma unroll
            for (int i = 0; i < 4; ++i)
                #pragma unroll
                for (int j = 0; j < 4; ++j)
                    acc[i][j] = fmaf(a[i], bb[j], acc[i][j]);
        }
        __syncthreads();
    }
    #pragma unroll
    for (int i = 0; i < 4; ++i) {
        float4 r = make_float4(acc[i][0], acc[i][1], acc[i][2], acc[i][3]);
        *(float4*)&Ob[(size_t)(bm + tm * 4 + i) * Ncol + bn + tn * 4] = r;
    }
}

// ---------------- SR conv (k=4,s=4) as gathered GEMM + BN --------------------
// A = w_sr viewed as [O=256][K=4096] (contiguous), B gathered from x.
__global__ __launch_bounds__(256) void conv_sr(
    const float* __restrict__ x, const float* __restrict__ wsr,
    const float* __restrict__ gam, const float* __restrict__ bet,
    const float* __restrict__ mu,  const float* __restrict__ var,
    float* __restrict__ xr) {
    __shared__ float As[16][64];
    __shared__ float Bs[16][64];
    const int b  = blockIdx.z;
    const float* xb = x + (size_t)b * CDIM * NDIM;
    const int bm = blockIdx.y * 64;
    const int bn = blockIdx.x * 64;
    const int tid = threadIdx.x;
    const int tm = tid >> 4, tn = tid & 15;

    float acc[4][4] = {};
    for (int k0 = 0; k0 < KSR; k0 += 16) {
        const int ar = tid >> 2, ac = (tid & 3) * 4;
        float4 a4 = *(const float4*)&wsr[(size_t)(bm + ar) * KSR + k0 + ac];
        As[ac + 0][ar] = a4.x; As[ac + 1][ar] = a4.y;
        As[ac + 2][ar] = a4.z; As[ac + 3][ar] = a4.w;

        const int br = tid >> 4, bc = (tid & 15) * 4;
        const int kk = k0 + br;
        const int c = kk >> 4, p = (kk >> 2) & 3, qq = kk & 3;
        const float* xc = xb + (size_t)c * NDIM;
        #pragma unroll
        for (int j = 0; j < 4; ++j) {
            const int m = bn + bc + j;
            const int hh = m >> 5, ww = m & 31;
            Bs[br][bc + j] = xc[(hh * 4 + p) * WDIM + ww * 4 + qq];
        }
        __syncthreads();
        #pragma unroll
        for (int q2 = 0; q2 < 16; ++q2) {
            float4 av = *(const float4*)&As[q2][tm * 4];
            float4 bv = *(const float4*)&Bs[q2][tn * 4];
            float a[4] = {av.x, av.y, av.z, av.w};
            float bb[4] = {bv.x, bv.y, bv.z, bv.w};
            #pragma unroll
            for (int i = 0; i < 4; ++i)
                #pragma unroll
                for (int j = 0; j < 4; ++j)
                    acc[i][j] = fmaf(a[i], bb[j], acc[i][j]);
        }
        __syncthreads();
    }
    float* Ob = xr + (size_t)b * CDIM * NKV;
    #pragma unroll
    for (int i = 0; i < 4; ++i) {
        const int o = bm + tm * 4 + i;
        const float inv = gam[o] * rsqrtf(var[o] + EPSBN);
        const float mb  = mu[o];
        const float be  = bet[o];
        float4 r;
        r.x = (acc[i][0] - mb) * inv + be;
        r.y = (acc[i][1] - mb) * inv + be;
        r.z = (acc[i][2] - mb) * inv + be;
        r.w = (acc[i][3] - mb) * inv + be;
        *(float4*)&Ob[(size_t)o * NKV + bn + tn * 4] = r;
    }
}

// ---------------- v = mean_n x, per (b,c) ------------------------------------
__global__ __launch_bounds__(256) void mean_v(const float* __restrict__ x,
                                              float* __restrict__ v) {
    const int bc = blockIdx.x;                // 0..511
    const float* xp = x + (size_t)bc * NDIM;
    float s = 0.f;
    for (int i = threadIdx.x; i < NDIM; i += 256) s += xp[i];
    __shared__ float red[256];
    red[threadIdx.x] = s;
    __syncthreads();
    for (int st = 128; st > 0; st >>= 1) {
        if (threadIdx.x < st) red[threadIdx.x] += red[threadIdx.x + st];
        __syncthreads();
    }
    if (threadIdx.x == 0) v[bc] = red[0] * (1.0f / NDIM);
}

// ---------------- alpha[b][o] = (w_proj@v)*inv ; bias[o] ---------------------
__global__ __launch_bounds__(256) void alpha_kernel(
    const float* __restrict__ wproj, const float* __restrict__ v,
    const float* __restrict__ gam, const float* __restrict__ bet,
    const float* __restrict__ mu,  const float* __restrict__ var,
    float* __restrict__ alpha, float* __restrict__ bias) {
    const int b = blockIdx.x;
    const int o = threadIdx.x;
    __shared__ float vs[CDIM];
    vs[o] = v[b * CDIM + o];
    __syncthreads();
    float p = 0.f;
    const float* wr = wproj + (size_t)o * CDIM;
    #pragma unroll 8
    for (int c = 0; c < CDIM; ++c) p = fmaf(wr[c], vs[c], p);
    const float inv = gam[o] * rsqrtf(var[o] + EPSBN);
    alpha[b * CDIM + o] = p * inv;
    if (b == 0) bias[o] = bet[o] - mu[o] * inv;
}

// ---------------- attention: per-head rowmax of q @ k ------------------------
// grid (N/1024, NHEADS, B), 256 threads, 2 passes x 2 n's per thread.
// k[b,h] (32x1024) staged in SMEM as [m][d] stride-36 (float4 reads, warp-uniform).
__global__ __launch_bounds__(256) void attn_kernel(
    const float* __restrict__ q, const float* __restrict__ k,
    float* __restrict__ attn) {
    extern __shared__ float ks[];  // [1024][36]
    const int b = blockIdx.z, h = blockIdx.y;
    const int n_base = blockIdx.x * 1024;
    const float* kb = k + ((size_t)b * CDIM + h * HD) * NKV;
    for (int idx = threadIdx.x; idx < HD * NKV; idx += 256) {
        const int d = idx >> 10, m = idx & 1023;
        ks[m * 36 + d] = kb[idx];
    }
    __syncthreads();
    const float scale = 0.17677669529663687f;  // 32^-0.5
    const float* qb = q + ((size_t)b * CDIM + h * HD) * NDIM;
    float* ob = attn + ((size_t)b * NHEADS + h) * NDIM;

    for (int pass = 0; pass < 2; ++pass) {
        const int n0 = n_base + pass * 512 + threadIdx.x;
        const int n1 = n0 + 256;
        float qa[HD], qc[HD];
        #pragma unroll
        for (int d = 0; d < HD; ++d) {
            qa[d] = qb[(size_t)d * NDIM + n0];
            qc[d] = qb[(size_t)d * NDIM + n1];
        }
        float ma = -INFINITY, mc = -INFINITY;
        for (int m = 0; m < NKV; ++m) {
            const float4* kp = (const float4*)&ks[m * 36];
            float a0 = 0, a1 = 0, a2 = 0, a3 = 0;
            float c0 = 0, c1 = 0, c2 = 0, c3 = 0;
            #pragma unroll
            for (int i = 0; i < 8; ++i) {
                float4 kv = kp[i];
                a0 = fmaf(qa[4 * i + 0], kv.x, a0); c0 = fmaf(qc[4 * i + 0], kv.x, c0);
                a1 = fmaf(qa[4 * i + 1], kv.y, a1); c1 = fmaf(qc[4 * i + 1], kv.y, c1);
                a2 = fmaf(qa[4 * i + 2], kv.z, a2); c2 = fmaf(qc[4 * i + 2], kv.z, c2);
                a3 = fmaf(qa[4 * i + 3], kv.w, a3); c3 = fmaf(qc[4 * i + 3], kv.w, c3);
            }
            ma = fmaxf(ma, (a0 + a1) + (a2 + a3));
            mc = fmaxf(mc, (c0 + c1) + (c2 + c3));
        }
        ob[n0] = ma * scale;
        ob[n1] = mc * scale;
    }
}

// ---------------- S[b][n] = sum_h attn --------------------------------------
__global__ __launch_bounds__(256) void reduce_attn(const float* __restrict__ attn,
                                                   float* __restrict__ S) {
    const int idx = blockIdx.x * 256 + threadIdx.x;  // over B*N
    const int b = idx >> 14, n = idx & (NDIM - 1);
    float s = 0.f;
    #pragma unroll
    for (int h = 0; h < NHEADS; ++h)
        s += attn[((size_t)b * NHEADS + h) * NDIM + n];
    S[idx] = s;
}

// ---------------- out[b][o][n] = alpha[b][o]*S[b][n] + bias[o] ---------------
__global__ __launch_bounds__(256) void final_kernel(
    const float* __restrict__ S, const float* __restrict__ alpha,
    const float* __restrict__ bias, float* __restrict__ out) {
    const size_t t = (size_t)blockIdx.x * 256 + threadIdx.x;
    const size_t idx4 = t * 4;                    // 4 consecutive n
    const int bo = (int)(idx4 >> 14);             // b*256 + o
    const int n  = (int)(idx4 & (NDIM - 1));
    const int b  = bo >> 8, o = bo & 255;
    const float a  = alpha[bo];
    const float bi = bias[o];
    float4 s = *(const float4*)&S[(size_t)b * NDIM + n];
    float4 r;
    r.x = fmaf(a, s.x, bi); r.y = fmaf(a, s.y, bi);
    r.z = fmaf(a, s.z, bi); r.w = fmaf(a, s.w, bi);
    *(float4*)&out[idx4] = r;
}

// ---------------- launch ------------------------------------------------------
extern "C" void kernel_launch(void* const* d_in, const int* in_sizes, int n_in,
                              void* d_out, int out_size) {
    const float* x      = (const float*)d_in[0];
    const float* w_q    = (const float*)d_in[1];
    const float* w_k    = (const float*)d_in[2];
    const float* w_sr   = (const float*)d_in[3];
    const float* sr_g   = (const float*)d_in[4];
    const float* sr_b   = (const float*)d_in[5];
    const float* sr_m   = (const float*)d_in[6];
    const float* sr_v   = (const float*)d_in[7];
    const float* w_proj = (const float*)d_in[8];
    const float* pj_g   = (const float*)d_in[9];
    const float* pj_b   = (const float*)d_in[10];
    const float* pj_m   = (const float*)d_in[11];
    const float* pj_v   = (const float*)d_in[12];
    float* out = (float*)d_out;

    float *q, *xr, *kk, *attn, *S, *v, *alpha, *bias;
    cudaGetSymbolAddress((void**)&q,     g_q);
    cudaGetSymbolAddress((void**)&xr,    g_xr);
    cudaGetSymbolAddress((void**)&kk,    g_k);
    cudaGetSymbolAddress((void**)&attn,  g_attn);
    cudaGetSymbolAddress((void**)&S,     g_S);
    cudaGetSymbolAddress((void**)&v,     g_v);
    cudaGetSymbolAddress((void**)&alpha, g_alpha);
    cudaGetSymbolAddress((void**)&bias,  g_bias);

    // allow 144 KB dynamic smem for attention
    static bool attr_set = false;
    (void)attr_set;
    cudaFuncSetAttribute(attn_kernel, cudaFuncAttributeMaxDynamicSharedMemorySize,
                         NKV * 36 * (int)sizeof(float));

    // 1. q = w_q @ x
    gemm_wx<<<dim3(NDIM / 64, CDIM / 64, BSZ), 256>>>(w_q, x, q, CDIM, NDIM);
    // 2. xr = BN(conv_sr(x))
    conv_sr<<<dim3(NKV / 64, CDIM / 64, BSZ), 256>>>(x, w_sr, sr_g, sr_b, sr_m, sr_v, xr);
    // 3. k = w_k @ xr
    gemm_wx<<<dim3(NKV / 64, CDIM / 64, BSZ), 256>>>(w_k, xr, kk, CDIM, NKV);
    // 4. v = mean(x)
    mean_v<<<BSZ * CDIM, 256>>>(x, v);
    // 5. alpha/bias
    alpha_kernel<<<BSZ, CDIM>>>(w_proj, v, pj_g, pj_b, pj_m, pj_v, alpha, bias);
    // 6. per-head attention rowmax
    attn_kernel<<<dim3(NDIM / 1024, NHEADS, BSZ), 256, NKV * 36 * sizeof(float)>>>(q, kk, attn);
    // 7. S = sum_h attn
    reduce_attn<<<BSZ * NDIM / 256, 256>>>(attn, S);
    // 8. out = alpha*S + bias
    final_kernel<<<(BSZ * CDIM * NDIM / 4) / 256, 256>>>(S, alpha, bias, out);
}

// round 2
// speedup vs baseline: 1.0697x; 1.0697x over previous
#include <cuda_runtime.h>
#include <math.h>

// Problem constants
#define BSZ    2
#define CDIM   256
#define NDIM   16384      // 128*128
#define HDIM   128
#define WDIM   128
#define SRF    4
#define NKV    1024       // 32*32
#define NHEADS 8
#define HD     32
#define EPSBN  1e-5f
#define KSR    4096       // CDIM*SRF*SRF

typedef unsigned long long u64;

// ---------------- f32x2 helpers (Blackwell packed fp32) ----------------------
__device__ __forceinline__ u64 pack2(float lo, float hi) {
    u64 r; asm("mov.b64 %0, {%1, %2};" : "=l"(r) : "f"(lo), "f"(hi)); return r;
}
__device__ __forceinline__ u64 fma2(u64 a, u64 b, u64 c) {
    u64 d; asm("fma.rn.f32x2 %0, %1, %2, %3;" : "=l"(d) : "l"(a), "l"(b), "l"(c)); return d;
}
__device__ __forceinline__ u64 add2(u64 a, u64 b) {
    u64 d; asm("add.rn.f32x2 %0, %1, %2;" : "=l"(d) : "l"(a), "l"(b)); return d;
}
__device__ __forceinline__ float2 unpack2(u64 a) {
    float lo, hi; asm("mov.b64 {%0, %1}, %2;" : "=f"(lo), "=f"(hi) : "l"(a));
    return make_float2(lo, hi);
}

// ---------------- scratch (device globals; no allocation allowed) ------------
__device__ float g_q   [BSZ * CDIM * NDIM];   // q as (b, o=h*32+d, n)
__device__ float g_xr  [BSZ * CDIM * NKV];    // spatial-reduced + BN
__device__ float g_k   [BSZ * CDIM * NKV];    // k as (b, o=h*32+d, m)
__device__ float g_attn[BSZ * NHEADS * NDIM]; // per-head max
__device__ float g_S   [BSZ * NDIM];          // sum over heads
__device__ float g_v   [BSZ * CDIM];          // mean-pooled x
__device__ float g_alpha[BSZ * CDIM];         // p * gamma/sqrt(var+eps)
__device__ float g_bias [CDIM];               // beta - mean*gamma/sqrt(var+eps)

// ---------------- generic W(OxK) @ X(b,K,Ncol) GEMM (f32x2) ------------------
// 64x64 tile, BK=16, 256 threads, 4x4 per thread.
__global__ __launch_bounds__(256) void gemm_wx(
    const float* __restrict__ W, const float* __restrict__ X,
    float* __restrict__ Out, int K, int Ncol) {
    __shared__ float As[16][64];  // [k][o]
    __shared__ float Bs[16][64];  // [k][n]
    const int b  = blockIdx.z;
    const float* Xb = X + (size_t)b * K * Ncol;
    float*       Ob = Out + (size_t)b * CDIM * Ncol;
    const int bm = blockIdx.y * 64;
    const int bn = blockIdx.x * 64;
    const int tid = threadIdx.x;
    const int tm = tid >> 4, tn = tid & 15;

    u64 acc[4][2] = {};
    for (int k0 = 0; k0 < K; k0 += 16) {
        const int ar = tid >> 2, ac = (tid & 3) * 4;
        float4 a4 = *(const float4*)&W[(size_t)(bm + ar) * K + k0 + ac];
        As[ac + 0][ar] = a4.x; As[ac + 1][ar] = a4.y;
        As[ac + 2][ar] = a4.z; As[ac + 3][ar] = a4.w;
        const int br = tid >> 4, bc = (tid & 15) * 4;
        *(float4*)&Bs[br][bc] = *(const float4*)&Xb[(size_t)(k0 + br) * Ncol + bn + bc];
        __syncthreads();
        #pragma unroll
        for (int kk = 0; kk < 16; ++kk) {
            float4 av = *(const float4*)&As[kk][tm * 4];
            ulonglong2 bv = *(const ulonglong2*)&Bs[kk][tn * 4];
            u64 a0 = pack2(av.x, av.x), a1 = pack2(av.y, av.y);
            u64 a2 = pack2(av.z, av.z), a3 = pack2(av.w, av.w);
            acc[0][0] = fma2(a0, bv.x, acc[0][0]); acc[0][1] = fma2(a0, bv.y, acc[0][1]);
            acc[1][0] = fma2(a1, bv.x, acc[1][0]); acc[1][1] = fma2(a1, bv.y, acc[1][1]);
            acc[2][0] = fma2(a2, bv.x, acc[2][0]); acc[2][1] = fma2(a2, bv.y, acc[2][1]);
            acc[3][0] = fma2(a3, bv.x, acc[3][0]); acc[3][1] = fma2(a3, bv.y, acc[3][1]);
        }
        __syncthreads();
    }
    #pragma unroll
    for (int i = 0; i < 4; ++i) {
        float2 lo = unpack2(acc[i][0]), hi = unpack2(acc[i][1]);
        float4 r = make_float4(lo.x, lo.y, hi.x, hi.y);
        *(float4*)&Ob[(size_t)(bm + tm * 4 + i) * Ncol + bn + tn * 4] = r;
    }
}

// ---------------- SR conv (k=4,s=4) as gathered GEMM + BN (f32x2) ------------
__global__ __launch_bounds__(256) void conv_sr(
    const float* __restrict__ x, const float* __restrict__ wsr,
    const float* __restrict__ gam, const float* __restrict__ bet,
    const float* __restrict__ mu,  const float* __restrict__ var,
    float* __restrict__ xr) {
    __shared__ float As[16][64];
    __shared__ float Bs[16][64];
    const int b  = blockIdx.z;
    const float* xb = x + (size_t)b * CDIM * NDIM;
    const int bm = blockIdx.y * 64;
    const int bn = blockIdx.x * 64;
    const int tid = threadIdx.x;
    const int tm = tid >> 4, tn = tid & 15;

    u64 acc[4][2] = {};
    for (int k0 = 0; k0 < KSR; k0 += 16) {
        const int ar = tid >> 2, ac = (tid & 3) * 4;
        float4 a4 = *(const float4*)&wsr[(size_t)(bm + ar) * KSR + k0 + ac];
        As[ac + 0][ar] = a4.x; As[ac + 1][ar] = a4.y;
        As[ac + 2][ar] = a4.z; As[ac + 3][ar] = a4.w;

        const int br = tid >> 4, bc = (tid & 15) * 4;
        const int kk = k0 + br;
        const int c = kk >> 4, p = (kk >> 2) & 3, qq = kk & 3;
        const float* xc = xb + (size_t)c * NDIM;
        #pragma unroll
        for (int j = 0; j < 4; ++j) {
            const int m = bn + bc + j;
            const int hh = m >> 5, ww = m & 31;
            Bs[br][bc + j] = xc[(hh * 4 + p) * WDIM + ww * 4 + qq];
        }
        __syncthreads();
        #pragma unroll
        for (int q2 = 0; q2 < 16; ++q2) {
            float4 av = *(const float4*)&As[q2][tm * 4];
            ulonglong2 bv = *(const ulonglong2*)&Bs[q2][tn * 4];
            u64 a0 = pack2(av.x, av.x), a1 = pack2(av.y, av.y);
            u64 a2 = pack2(av.z, av.z), a3 = pack2(av.w, av.w);
            acc[0][0] = fma2(a0, bv.x, acc[0][0]); acc[0][1] = fma2(a0, bv.y, acc[0][1]);
            acc[1][0] = fma2(a1, bv.x, acc[1][0]); acc[1][1] = fma2(a1, bv.y, acc[1][1]);
            acc[2][0] = fma2(a2, bv.x, acc[2][0]); acc[2][1] = fma2(a2, bv.y, acc[2][1]);
            acc[3][0] = fma2(a3, bv.x, acc[3][0]); acc[3][1] = fma2(a3, bv.y, acc[3][1]);
        }
        __syncthreads();
    }
    float* Ob = xr + (size_t)b * CDIM * NKV;
    #pragma unroll
    for (int i = 0; i < 4; ++i) {
        const int o = bm + tm * 4 + i;
        const float inv = gam[o] * rsqrtf(var[o] + EPSBN);
        const float mb  = mu[o];
        const float be  = bet[o];
        float2 lo = unpack2(acc[i][0]), hi = unpack2(acc[i][1]);
        float4 r;
        r.x = (lo.x - mb) * inv + be;
        r.y = (lo.y - mb) * inv + be;
        r.z = (hi.x - mb) * inv + be;
        r.w = (hi.y - mb) * inv + be;
        *(float4*)&Ob[(size_t)o * NKV + bn + tn * 4] = r;
    }
}

// ---------------- v = mean_n x, per (b,c) ------------------------------------
__global__ __launch_bounds__(256) void mean_v(const float* __restrict__ x,
                                              float* __restrict__ v) {
    const int bc = blockIdx.x;                // 0..511
    const float* xp = x + (size_t)bc * NDIM;
    float s = 0.f;
    for (int i = threadIdx.x * 4; i < NDIM; i += 256 * 4) {
        float4 t = *(const float4*)&xp[i];
        s += (t.x + t.y) + (t.z + t.w);
    }
    __shared__ float red[256];
    red[threadIdx.x] = s;
    __syncthreads();
    for (int st = 128; st > 0; st >>= 1) {
        if (threadIdx.x < st) red[threadIdx.x] += red[threadIdx.x + st];
        __syncthreads();
    }
    if (threadIdx.x == 0) v[bc] = red[0] * (1.0f / NDIM);
}

// ---------------- alpha[b][o] = (w_proj@v)*inv ; bias[o] ---------------------
__global__ __launch_bounds__(256) void alpha_kernel(
    const float* __restrict__ wproj, const float* __restrict__ v,
    const float* __restrict__ gam, const float* __restrict__ bet,
    const float* __restrict__ mu,  const float* __restrict__ var,
    float* __restrict__ alpha, float* __restrict__ bias) {
    const int b = blockIdx.x;
    const int o = threadIdx.x;
    __shared__ float vs[CDIM];
    vs[o] = v[b * CDIM + o];
    __syncthreads();
    float p = 0.f;
    const float* wr = wproj + (size_t)o * CDIM;
    #pragma unroll 8
    for (int c = 0; c < CDIM; ++c) p = fmaf(wr[c], vs[c], p);
    const float inv = gam[o] * rsqrtf(var[o] + EPSBN);
    alpha[b * CDIM + o] = p * inv;
    if (b == 0) bias[o] = bet[o] - mu[o] * inv;
}

// ---------------- attention: per-head rowmax of q @ k (f32x2) ----------------
// grid (N/1024, NHEADS, B), 256 threads, 2 passes x 2 n's per thread.
// k[b,h] (32x1024) staged in SMEM as [m][d] stride-36; row base 16B-aligned.
__global__ __launch_bounds__(256) void attn_kernel(
    const float* __restrict__ q, const float* __restrict__ k,
    float* __restrict__ attn) {
    extern __shared__ float ks[];  // [1024][36]
    const int b = blockIdx.z, h = blockIdx.y;
    const int n_base = blockIdx.x * 1024;
    const float* kb = k + ((size_t)b * CDIM + h * HD) * NKV;
    for (int idx = threadIdx.x; idx < HD * NKV; idx += 256) {
        const int d = idx >> 10, m = idx & 1023;
        ks[m * 36 + d] = kb[idx];
    }
    __syncthreads();
    const float scale = 0.17677669529663687f;  // 32^-0.5
    const float* qb = q + ((size_t)b * CDIM + h * HD) * NDIM;
    float* ob = attn + ((size_t)b * NHEADS + h) * NDIM;

    for (int pass = 0; pass < 2; ++pass) {
        const int n0 = n_base + pass * 512 + threadIdx.x;
        const int n1 = n0 + 256;
        // q packed along d: qa2[i] = (q[2i], q[2i+1]) for n0; qc2 for n1
        u64 qa2[16], qc2[16];
        #pragma unroll
        for (int i = 0; i < 16; ++i) {
            qa2[i] = pack2(qb[(size_t)(2 * i) * NDIM + n0],
                           qb[(size_t)(2 * i + 1) * NDIM + n0]);
            qc2[i] = pack2(qb[(size_t)(2 * i) * NDIM + n1],
                           qb[(size_t)(2 * i + 1) * NDIM + n1]);
        }
        float ma = -INFINITY, mc = -INFINITY;
        for (int m = 0; m < NKV; ++m) {
            const ulonglong2* kp = (const ulonglong2*)&ks[m * 36];
            u64 a0 = 0, a1 = 0, a2 = 0, a3 = 0;   // (0,0) bit pattern
            u64 c0 = 0, c1 = 0, c2 = 0, c3 = 0;
            #pragma unroll
            for (int i = 0; i < 8; ++i) {
                ulonglong2 kv = kp[i];               // d = 4i..4i+3 as two f32x2
                a0 = fma2(qa2[2 * i],     kv.x, a0);
                a1 = fma2(qa2[2 * i + 1], kv.y, a1);
                c0 = fma2(qc2[2 * i],     kv.x, c0);
                c1 = fma2(qc2[2 * i + 1], kv.y, c1);
                // rotate chains to keep 8 independent FMA streams
                { u64 t = a2; a2 = a0; a0 = t; }
                { u64 t = a3; a3 = a1; a1 = t; }
                { u64 t = c2; c2 = c0; c0 = t; }
                { u64 t = c3; c3 = c1; c1 = t; }
            }
            u64 asum = add2(add2(a0, a1), add2(a2, a3));
            u64 csum = add2(add2(c0, c1), add2(c2, c3));
            float2 af = unpack2(asum);
            float2 cf = unpack2(csum);
            ma = fmaxf(ma, af.x + af.y);
            mc = fmaxf(mc, cf.x + cf.y);
        }
        ob[n0] = ma * scale;
        ob[n1] = mc * scale;
    }
}

// ---------------- S[b][n] = sum_h attn --------------------------------------
__global__ __launch_bounds__(256) void reduce_attn(const float* __restrict__ attn,
                                                   float* __restrict__ S) {
    const int idx = blockIdx.x * 256 + threadIdx.x;  // over B*N
    const int b = idx >> 14, n = idx & (NDIM - 1);
    float s = 0.f;
    #pragma unroll
    for (int h = 0; h < NHEADS; ++h)
        s += attn[((size_t)b * NHEADS + h) * NDIM + n];
    S[idx] = s;
}

// ---------------- out[b][o][n] = alpha[b][o]*S[b][n] + bias[o] ---------------
__global__ __launch_bounds__(256) void final_kernel(
    const float* __restrict__ S, const float* __restrict__ alpha,
    const float* __restrict__ bias, float* __restrict__ out) {
    const size_t t = (size_t)blockIdx.x * 256 + threadIdx.x;
    const size_t idx4 = t * 4;                    // 4 consecutive n
    const int bo = (int)(idx4 >> 14);             // b*256 + o
    const int n  = (int)(idx4 & (NDIM - 1));
    const int b  = bo >> 8, o = bo & 255;
    const float a  = alpha[bo];
    const float bi = bias[o];
    float4 s = *(const float4*)&S[(size_t)b * NDIM + n];
    float4 r;
    r.x = fmaf(a, s.x, bi); r.y = fmaf(a, s.y, bi);
    r.z = fmaf(a, s.z, bi); r.w = fmaf(a, s.w, bi);
    *(float4*)&out[idx4] = r;
}

// ---------------- launch ------------------------------------------------------
extern "C" void kernel_launch(void* const* d_in, const int* in_sizes, int n_in,
                              void* d_out, int out_size) {
    const float* x      = (const float*)d_in[0];
    const float* w_q    = (const float*)d_in[1];
    const float* w_k    = (const float*)d_in[2];
    const float* w_sr   = (const float*)d_in[3];
    const float* sr_g   = (const float*)d_in[4];
    const float* sr_b   = (const float*)d_in[5];
    const float* sr_m   = (const float*)d_in[6];
    const float* sr_v   = (const float*)d_in[7];
    const float* w_proj = (const float*)d_in[8];
    const float* pj_g   = (const float*)d_in[9];
    const float* pj_b   = (const float*)d_in[10];
    const float* pj_m   = (const float*)d_in[11];
    const float* pj_v   = (const float*)d_in[12];
    float* out = (float*)d_out;

    float *q, *xr, *kk, *attn, *S, *v, *alpha, *bias;
    cudaGetSymbolAddress((void**)&q,     g_q);
    cudaGetSymbolAddress((void**)&xr,    g_xr);
    cudaGetSymbolAddress((void**)&kk,    g_k);
    cudaGetSymbolAddress((void**)&attn,  g_attn);
    cudaGetSymbolAddress((void**)&S,     g_S);
    cudaGetSymbolAddress((void**)&v,     g_v);
    cudaGetSymbolAddress((void**)&alpha, g_alpha);
    cudaGetSymbolAddress((void**)&bias,  g_bias);

    cudaFuncSetAttribute(attn_kernel, cudaFuncAttributeMaxDynamicSharedMemorySize,
                         NKV * 36 * (int)sizeof(float));

    // 1. q = w_q @ x
    gemm_wx<<<dim3(NDIM / 64, CDIM / 64, BSZ), 256>>>(w_q, x, q, CDIM, NDIM);
    // 2. xr = BN(conv_sr(x))
    conv_sr<<<dim3(NKV / 64, CDIM / 64, BSZ), 256>>>(x, w_sr, sr_g, sr_b, sr_m, sr_v, xr);
    // 3. k = w_k @ xr
    gemm_wx<<<dim3(NKV / 64, CDIM / 64, BSZ), 256>>>(w_k, xr, kk, CDIM, NKV);
    // 4. v = mean(x)
    mean_v<<<BSZ * CDIM, 256>>>(x, v);
    // 5. alpha/bias
    alpha_kernel<<<BSZ, CDIM>>>(w_proj, v, pj_g, pj_b, pj_m, pj_v, alpha, bias);
    // 6. per-head attention rowmax
    attn_kernel<<<dim3(NDIM / 1024, NHEADS, BSZ), 256, NKV * 36 * sizeof(float)>>>(q, kk, attn);
    // 7. S = sum_h attn
    reduce_attn<<<BSZ * NDIM / 256, 256>>>(attn, S);
    // 8. out = alpha*S + bias
    final_kernel<<<(BSZ * CDIM * NDIM / 4) / 256, 256>>>(S, alpha, bias, out);
}

// round 4
// speedup vs baseline: 1.6539x; 1.5461x over previous
#include <cuda_runtime.h>
#include <cuda_bf16.h>
#include <math.h>
#include <cstdint>

// Problem constants
#define BSZ    2
#define CDIM   256
#define NDIM   16384      // 128*128
#define HDIM   128
#define WDIM   128
#define NKV    1024       // 32*32
#define NHEADS 8
#define HD     32
#define EPSBN  1e-5f
#define KSR    4096       // CDIM*4*4

typedef unsigned long long u64;
typedef unsigned int u32;
typedef unsigned short u16;

// ===================== f32x2 helpers ==========================================
__device__ __forceinline__ u64 pack2(float lo, float hi) {
    u64 r; asm("mov.b64 %0, {%1, %2};" : "=l"(r) : "f"(lo), "f"(hi)); return r;
}
__device__ __forceinline__ u64 fma2(u64 a, u64 b, u64 c) {
    u64 d; asm("fma.rn.f32x2 %0, %1, %2, %3;" : "=l"(d) : "l"(a), "l"(b), "l"(c)); return d;
}
__device__ __forceinline__ float2 unpack2(u64 a) {
    float lo, hi; asm("mov.b64 {%0, %1}, %2;" : "=f"(lo), "=f"(hi) : "l"(a));
    return make_float2(lo, hi);
}

// ===================== mma/ldmatrix helpers (baseline PTX, sm_80+) ===========
__device__ __forceinline__ u32 smem_u32(const void* p) {
    u32 a; asm("{ .reg .u64 t; cvta.to.shared.u64 t, %1; cvt.u32.u64 %0, t; }"
               : "=r"(a) : "l"(p)); return a;
}
__device__ __forceinline__ void ldm_x4(u32 r[4], u32 addr) {
    asm volatile("ldmatrix.sync.aligned.m8n8.x4.shared.b16 {%0,%1,%2,%3}, [%4];"
                 : "=r"(r[0]), "=r"(r[1]), "=r"(r[2]), "=r"(r[3]) : "r"(addr));
}
__device__ __forceinline__ void mma_z(float& c0, float& c1, float& c2, float& c3,
                                      u32 a0, u32 a1, u32 a2, u32 a3,
                                      u32 b0, u32 b1) {
    asm volatile("mma.sync.aligned.m16n8k16.row.col.f32.bf16.bf16.f32 "
                 "{%0,%1,%2,%3}, {%4,%5,%6,%7}, {%8,%9}, {%10,%10,%10,%10};"
                 : "=f"(c0), "=f"(c1), "=f"(c2), "=f"(c3)
                 : "r"(a0), "r"(a1), "r"(a2), "r"(a3), "r"(b0), "r"(b1), "f"(0.0f));
}
__device__ __forceinline__ void mma_a(float& c0, float& c1, float& c2, float& c3,
                                      u32 a0, u32 a1, u32 a2, u32 a3,
                                      u32 b0, u32 b1) {
    asm volatile("mma.sync.aligned.m16n8k16.row.col.f32.bf16.bf16.f32 "
                 "{%0,%1,%2,%3}, {%4,%5,%6,%7}, {%8,%9}, {%0,%1,%2,%3};"
                 : "+f"(c0), "+f"(c1), "+f"(c2), "+f"(c3)
                 : "r"(a0), "r"(a1), "r"(a2), "r"(a3), "r"(b0), "r"(b1));
}
__device__ __forceinline__ u32 sw128(u32 b) { return b ^ ((b >> 3) & 0x70); }

// ===================== scratch ================================================
__device__ u16  g_qbf [BSZ * NHEADS * NDIM * 64];  // (bh, n, hi[32]|lo[32]) bf16
__device__ u16  g_kbf [BSZ * NHEADS * NKV  * 64];  // (bh, m, hi[32]|lo[32]) bf16
__device__ float g_xr  [BSZ * CDIM * NKV];
__device__ float g_attn[BSZ * NHEADS * NDIM];
__device__ float g_S   [BSZ * NDIM];
__device__ float g_v   [BSZ * CDIM];
__device__ float g_alpha[BSZ * CDIM];
__device__ float g_bias [CDIM];

// ===================== GEMM W@X with split-bf16 epilogue =====================
__global__ __launch_bounds__(256) void gemm_split(
    const float* __restrict__ W, const float* __restrict__ X,
    u16* __restrict__ Out, int Ncol) {
    __shared__ float As[16][64];
    __shared__ float Bs[16][64];
    const int b  = blockIdx.z;
    const float* Xb = X + (size_t)b * CDIM * Ncol;
    const int bm = blockIdx.y * 64;
    const int bn = blockIdx.x * 64;
    const int tid = threadIdx.x;
    const int tm = tid >> 4, tn = tid & 15;

    u64 acc[4][2] = {};
    for (int k0 = 0; k0 < CDIM; k0 += 16) {
        const int ar = tid >> 2, ac = (tid & 3) * 4;
        float4 a4 = *(const float4*)&W[(size_t)(bm + ar) * CDIM + k0 + ac];
        As[ac + 0][ar] = a4.x; As[ac + 1][ar] = a4.y;
        As[ac + 2][ar] = a4.z; As[ac + 3][ar] = a4.w;
        const int br = tid >> 4, bc = (tid & 15) * 4;
        *(float4*)&Bs[br][bc] = *(const float4*)&Xb[(size_t)(k0 + br) * Ncol + bn + bc];
        __syncthreads();
        #pragma unroll
        for (int kk = 0; kk < 16; ++kk) {
            float4 av = *(const float4*)&As[kk][tm * 4];
            ulonglong2 bv = *(const ulonglong2*)&Bs[kk][tn * 4];
            u64 a0 = pack2(av.x, av.x), a1 = pack2(av.y, av.y);
            u64 a2 = pack2(av.z, av.z), a3 = pack2(av.w, av.w);
            acc[0][0] = fma2(a0, bv.x, acc[0][0]); acc[0][1] = fma2(a0, bv.y, acc[0][1]);
            acc[1][0] = fma2(a1, bv.x, acc[1][0]); acc[1][1] = fma2(a1, bv.y, acc[1][1]);
            acc[2][0] = fma2(a2, bv.x, acc[2][0]); acc[2][1] = fma2(a2, bv.y, acc[2][1]);
            acc[3][0] = fma2(a3, bv.x, acc[3][0]); acc[3][1] = fma2(a3, bv.y, acc[3][1]);
        }
        __syncthreads();
    }
    const int o0 = bm + tm * 4;           // 4 consecutive o, same head
    const int h  = o0 >> 5;
    const int d0 = o0 & 31;
    const int bh = b * NHEADS + h;
    #pragma unroll
    for (int j = 0; j < 4; ++j) {
        const int col = bn + tn * 4 + j;
        u64 hi_pack = 0, lo_pack = 0;
        #pragma unroll
        for (int i = 0; i < 4; ++i) {
            float2 f = unpack2(acc[i][j >> 1]);
            float v = (j & 1) ? f.y : f.x;
            __nv_bfloat16 hb = __float2bfloat16_rn(v);
            float hf = __bfloat162float(hb);
            __nv_bfloat16 lb = __float2bfloat16_rn(v - hf);
            hi_pack |= (u64)__bfloat16_as_ushort(hb) << (16 * i);
            lo_pack |= (u64)__bfloat16_as_ushort(lb) << (16 * i);
        }
        u16* base = Out + ((size_t)bh * Ncol + col) * 64 + d0;
        *(u64*)base        = hi_pack;
        *(u64*)(base + 32) = lo_pack;
    }
}

// ---------------- SR conv (k=4,s=4) as gathered GEMM + BN (f32x2) ------------
__global__ __launch_bounds__(256) void conv_sr(
    const float* __restrict__ x, const float* __restrict__ wsr,
    const float* __restrict__ gam, const float* __restrict__ bet,
    const float* __restrict__ mu,  const float* __restrict__ var,
    float* __restrict__ xr) {
    __shared__ float As[16][64];
    __shared__ float Bs[16][64];
    const int b  = blockIdx.z;
    const float* xb = x + (size_t)b * CDIM * NDIM;
    const int bm = blockIdx.y * 64;
    const int bn = blockIdx.x * 64;
    const int tid = threadIdx.x;
    const int tm = tid >> 4, tn = tid & 15;

    u64 acc[4][2] = {};
    for (int k0 = 0; k0 < KSR; k0 += 16) {
        const int ar = tid >> 2, ac = (tid & 3) * 4;
        float4 a4 = *(const float4*)&wsr[(size_t)(bm + ar) * KSR + k0 + ac];
        As[ac + 0][ar] = a4.x; As[ac + 1][ar] = a4.y;
        As[ac + 2][ar] = a4.z; As[ac + 3][ar] = a4.w;

        const int br = tid >> 4, bc = (tid & 15) * 4;
        const int kk = k0 + br;
        const int c = kk >> 4, p = (kk >> 2) & 3, qq = kk & 3;
        const float* xc = xb + (size_t)c * NDIM;
        #pragma unroll
        for (int j = 0; j < 4; ++j) {
            const int m = bn + bc + j;
            const int hh = m >> 5, ww = m & 31;
            Bs[br][bc + j] = xc[(hh * 4 + p) * WDIM + ww * 4 + qq];
        }
        __syncthreads();
        #pragma unroll
        for (int q2 = 0; q2 < 16; ++q2) {
            float4 av = *(const float4*)&As[q2][tm * 4];
            ulonglong2 bv = *(const ulonglong2*)&Bs[q2][tn * 4];
            u64 a0 = pack2(av.x, av.x), a1 = pack2(av.y, av.y);
            u64 a2 = pack2(av.z, av.z), a3 = pack2(av.w, av.w);
            acc[0][0] = fma2(a0, bv.x, acc[0][0]); acc[0][1] = fma2(a0, bv.y, acc[0][1]);
            acc[1][0] = fma2(a1, bv.x, acc[1][0]); acc[1][1] = fma2(a1, bv.y, acc[1][1]);
            acc[2][0] = fma2(a2, bv.x, acc[2][0]); acc[2][1] = fma2(a2, bv.y, acc[2][1]);
            acc[3][0] = fma2(a3, bv.x, acc[3][0]); acc[3][1] = fma2(a3, bv.y, acc[3][1]);
        }
        __syncthreads();
    }
    float* Ob = xr + (size_t)b * CDIM * NKV;
    #pragma unroll
    for (int i = 0; i < 4; ++i) {
        const int o = bm + tm * 4 + i;
        const float inv = gam[o] * rsqrtf(var[o] + EPSBN);
        const float mb  = mu[o];
        const float be  = bet[o];
        float2 lo = unpack2(acc[i][0]), hi = unpack2(acc[i][1]);
        float4 r;
        r.x = (lo.x - mb) * inv + be;
        r.y = (lo.y - mb) * inv + be;
        r.z = (hi.x - mb) * inv + be;
        r.w = (hi.y - mb) * inv + be;
        *(float4*)&Ob[(size_t)o * NKV + bn + tn * 4] = r;
    }
}

// ---------------- v = mean_n x ------------------------------------------------
__global__ __launch_bounds__(256) void mean_v(const float* __restrict__ x,
                                              float* __restrict__ v) {
    const int bc = blockIdx.x;
    const float* xp = x + (size_t)bc * NDIM;
    float s = 0.f;
    for (int i = threadIdx.x * 4; i < NDIM; i += 256 * 4) {
        float4 t = *(const float4*)&xp[i];
        s += (t.x + t.y) + (t.z + t.w);
    }
    __shared__ float red[256];
    red[threadIdx.x] = s;
    __syncthreads();
    for (int st = 128; st > 0; st >>= 1) {
        if (threadIdx.x < st) red[threadIdx.x] += red[threadIdx.x + st];
        __syncthreads();
    }
    if (threadIdx.x == 0) v[bc] = red[0] * (1.0f / NDIM);
}

// ---------------- alpha/bias --------------------------------------------------
__global__ __launch_bounds__(256) void alpha_kernel(
    const float* __restrict__ wproj, const float* __restrict__ v,
    const float* __restrict__ gam, const float* __restrict__ bet,
    const float* __restrict__ mu,  const float* __restrict__ var,
    float* __restrict__ alpha, float* __restrict__ bias) {
    const int b = blockIdx.x;
    const int o = threadIdx.x;
    __shared__ float vs[CDIM];
    vs[o] = v[b * CDIM + o];
    __syncthreads();
    float p = 0.f;
    const float* wr = wproj + (size_t)o * CDIM;
    #pragma unroll 8
    for (int c = 0; c < CDIM; ++c) p = fmaf(wr[c], vs[c], p);
    const float inv = gam[o] * rsqrtf(var[o] + EPSBN);
    alpha[b * CDIM + o] = p * inv;
    if (b == 0) bias[o] = bet[o] - mu[o] * inv;
}

// ===================== mma.sync attention (HMMA fallback path) ================
// grid = 128: blockIdx.x = bh*8 + seg; block = 128 threads (4 warps).
// smem: ks[1024][64]bf16 swizzled @0 (128KB), qs[128][64]bf16 swizzled @131072.
#define SM_QOFF 131072
#define SM_TOT  147456
#define NTILES  16

__global__ __launch_bounds__(128, 1)
void attn_mma(const u16* __restrict__ qbf, const u16* __restrict__ kbf,
              float* __restrict__ attn) {
    extern __shared__ char smem[];
    const u32 sb  = smem_u32(smem);
    const u32 ksb = sb;
    const u32 qsb = sb + SM_QOFF;
    const int tid = threadIdx.x;
    const int wid = tid >> 5, l = tid & 31;
    const int bh  = blockIdx.x >> 3;
    const int seg = blockIdx.x & 7;

    // ---- stage k (1024 rows x 128B) into smem, swizzled ----
    {
        const uint4* ksrc = (const uint4*)(kbf + (size_t)bh * NKV * 64);
        for (int idx = tid; idx < NKV * 8; idx += 128) {
            const int row = idx >> 3, c = idx & 7;
            *(uint4*)(smem + sw128(row * 128 + c * 16)) = ksrc[idx];
        }
    }
    __syncthreads();

    // ---- per-lane ldmatrix addresses ----
    // B: lane l -> matrix m=l/8; row = kv0 + (l%8) + ((l&16)?8:0); chunk = 2s + ((l>>3)&1)
    const int brow = (l & 7) + ((l & 16) >> 1);
    u32 baddr[4];
    #pragma unroll
    for (int s = 0; s < 4; ++s)
        baddr[s] = ksb + brow * 128 + ((u32)((2 * s + ((l >> 3) & 1)) ^ (l & 7)) << 4);

    // A: lane l -> row = Rt + (l%8) + (l&8); chunk = 2s + ((l>>4)&1)
    const int arow = (l & 7) + (l & 8);
    u32 aaddr[4];
    #pragma unroll
    for (int s = 0; s < 4; ++s)
        aaddr[s] = qsb + arow * 128 + ((u32)((2 * s + ((l >> 4) & 1)) ^ (l & 7)) << 4);

    const float scale = 0.17677669529663687f;  // 32^-0.5
    float* ob = attn + (size_t)bh * NDIM;

    for (int t = 0; t < NTILES; ++t) {
        const int n_base = (seg * NTILES + t) * 128;
        // store this block's q tile (thread -> its own row tid); each warp only
        // reads back its own 32 rows -> __syncwarp suffices.
        {
            const uint4* qsrc = (const uint4*)(qbf + ((size_t)bh * NDIM + n_base) * 64);
            #pragma unroll
            for (int j = 0; j < 8; ++j)
                *(uint4*)(smem + SM_QOFF + sw128(tid * 128 + j * 16)) = qsrc[(size_t)tid * 8 + j];
        }
        __syncwarp();

        // A fragments: 2 m-tiles x 4 k16-steps (qhi s=0,1 ; qlo s=2,3)
        u32 a[2][4][4];
        #pragma unroll
        for (int mt = 0; mt < 2; ++mt) {
            const u32 roff = (u32)(wid * 32 + mt * 16) * 128;
            #pragma unroll
            for (int s = 0; s < 4; ++s)
                ldm_x4(a[mt][s], aaddr[s] + roff);
        }
        __syncwarp();

        float rmax[2][2] = {{-INFINITY, -INFINITY}, {-INFINITY, -INFINITY}};
        for (int kv = 0; kv < 64; ++kv) {
            const u32 off = (u32)kv * 2048;
            u32 bh0[4], bh1[4], bl0[4], bl1[4];
            ldm_x4(bh0, baddr[0] + off);   // khi d0-15  : [g0b0,g0b1,g1b0,g1b1]
            ldm_x4(bh1, baddr[1] + off);   // khi d16-31
            ldm_x4(bl0, baddr[2] + off);   // klo d0-15
            ldm_x4(bl1, baddr[3] + off);   // klo d16-31
            #pragma unroll
            for (int mt = 0; mt < 2; ++mt) {
                #pragma unroll
                for (int g = 0; g < 2; ++g) {
                    float c0, c1, c2, c3;
                    mma_z(c0, c1, c2, c3, a[mt][0][0], a[mt][0][1], a[mt][0][2], a[mt][0][3],
                          bh0[2 * g], bh0[2 * g + 1]);                       // qhi*khi (d0-15)
                    mma_a(c0, c1, c2, c3, a[mt][1][0], a[mt][1][1], a[mt][1][2], a[mt][1][3],
                          bh1[2 * g], bh1[2 * g + 1]);                       // qhi*khi (d16-31)
                    mma_a(c0, c1, c2, c3, a[mt][0][0], a[mt][0][1], a[mt][0][2], a[mt][0][3],
                          bl0[2 * g], bl0[2 * g + 1]);                       // qhi*klo (d0-15)
                    mma_a(c0, c1, c2, c3, a[mt][1][0], a[mt][1][1], a[mt][1][2], a[mt][1][3],
                          bl1[2 * g], bl1[2 * g + 1]);                       // qhi*klo (d16-31)
                    mma_a(c0, c1, c2, c3, a[mt][2][0], a[mt][2][1], a[mt][2][2], a[mt][2][3],
                          bh0[2 * g], bh0[2 * g + 1]);                       // qlo*khi (d0-15)
                    mma_a(c0, c1, c2, c3, a[mt][3][0], a[mt][3][1], a[mt][3][2], a[mt][3][3],
                          bh1[2 * g], bh1[2 * g + 1]);                       // qlo*khi (d16-31)
                    rmax[mt][0] = fmaxf(rmax[mt][0], fmaxf(c0, c1));
                    rmax[mt][1] = fmaxf(rmax[mt][1], fmaxf(c2, c3));
                }
            }
        }
        // reduce across the 4 lanes sharing a row (cols)
        #pragma unroll
        for (int mt = 0; mt < 2; ++mt)
            #pragma unroll
            for (int rr = 0; rr < 2; ++rr) {
                float v = rmax[mt][rr];
                v = fmaxf(v, __shfl_xor_sync(0xffffffffu, v, 1));
                v = fmaxf(v, __shfl_xor_sync(0xffffffffu, v, 2));
                rmax[mt][rr] = v;
            }
        if ((l & 3) == 0) {
            const int rbase = n_base + wid * 32;
            #pragma unroll
            for (int mt = 0; mt < 2; ++mt) {
                ob[rbase + mt * 16 + (l >> 2) + 0] = rmax[mt][0] * scale;
                ob[rbase + mt * 16 + (l >> 2) + 8] = rmax[mt][1] * scale;
            }
        }
        __syncwarp();
    }
}

// ---------------- S[b][n] = sum_h attn ----------------------------------------
__global__ __launch_bounds__(256) void reduce_attn(const float* __restrict__ attn,
                                                   float* __restrict__ S) {
    const int idx = blockIdx.x * 256 + threadIdx.x;
    const int b = idx >> 14, n = idx & (NDIM - 1);
    float s = 0.f;
    #pragma unroll
    for (int h = 0; h < NHEADS; ++h)
        s += attn[((size_t)b * NHEADS + h) * NDIM + n];
    S[idx] = s;
}

// ---------------- out = alpha*S + bias -----------------------------------------
__global__ __launch_bounds__(256) void final_kernel(
    const float* __restrict__ S, const float* __restrict__ alpha,
    const float* __restrict__ bias, float* __restrict__ out) {
    const size_t t = (size_t)blockIdx.x * 256 + threadIdx.x;
    const size_t idx4 = t * 4;
    const int bo = (int)(idx4 >> 14);
    const int n  = (int)(idx4 & (NDIM - 1));
    const int b  = bo >> 8, o = bo & 255;
    const float a  = alpha[bo];
    const float bi = bias[o];
    float4 s = *(const float4*)&S[(size_t)b * NDIM + n];
    float4 r;
    r.x = fmaf(a, s.x, bi); r.y = fmaf(a, s.y, bi);
    r.z = fmaf(a, s.z, bi); r.w = fmaf(a, s.w, bi);
    *(float4*)&out[idx4] = r;
}

// ===================== launch ==================================================
extern "C" void kernel_launch(void* const* d_in, const int* in_sizes, int n_in,
                              void* d_out, int out_size) {
    const float* x      = (const float*)d_in[0];
    const float* w_q    = (const float*)d_in[1];
    const float* w_k    = (const float*)d_in[2];
    const float* w_sr   = (const float*)d_in[3];
    const float* sr_g   = (const float*)d_in[4];
    const float* sr_b   = (const float*)d_in[5];
    const float* sr_m   = (const float*)d_in[6];
    const float* sr_v   = (const float*)d_in[7];
    const float* w_proj = (const float*)d_in[8];
    const float* pj_g   = (const float*)d_in[9];
    const float* pj_b   = (const float*)d_in[10];
    const float* pj_m   = (const float*)d_in[11];
    const float* pj_v   = (const float*)d_in[12];
    float* out = (float*)d_out;

    u16  *qbf, *kbf;
    float *xr, *attn, *S, *v, *alpha, *bias;
    cudaGetSymbolAddress((void**)&qbf,   g_qbf);
    cudaGetSymbolAddress((void**)&kbf,   g_kbf);
    cudaGetSymbolAddress((void**)&xr,    g_xr);
    cudaGetSymbolAddress((void**)&attn,  g_attn);
    cudaGetSymbolAddress((void**)&S,     g_S);
    cudaGetSymbolAddress((void**)&v,     g_v);
    cudaGetSymbolAddress((void**)&alpha, g_alpha);
    cudaGetSymbolAddress((void**)&bias,  g_bias);

    cudaFuncSetAttribute(attn_mma, cudaFuncAttributeMaxDynamicSharedMemorySize, SM_TOT);

    // 1. q split-bf16 = w_q @ x
    gemm_split<<<dim3(NDIM / 64, CDIM / 64, BSZ), 256>>>(w_q, x, qbf, NDIM);
    // 2. xr = BN(conv_sr(x))
    conv_sr<<<dim3(NKV / 64, CDIM / 64, BSZ), 256>>>(x, w_sr, sr_g, sr_b, sr_m, sr_v, xr);
    // 3. k split-bf16 = w_k @ xr
    gemm_split<<<dim3(NKV / 64, CDIM / 64, BSZ), 256>>>(w_k, xr, kbf, NKV);
    // 4. v = mean(x)
    mean_v<<<BSZ * CDIM, 256>>>(x, v);
    // 5. alpha/bias
    alpha_kernel<<<BSZ, CDIM>>>(w_proj, v, pj_g, pj_b, pj_m, pj_v, alpha, bias);
    // 6. tensor-core (HMMA) attention rowmax
    attn_mma<<<128, 128, SM_TOT>>>(qbf, kbf, attn);
    // 7. S = sum_h attn
    reduce_attn<<<BSZ * NDIM / 256, 256>>>(attn, S);
    // 8. out = alpha*S + bias
    final_kernel<<<(BSZ * CDIM * NDIM / 4) / 256, 256>>>(S, alpha, bias, out);
}

// round 5
// speedup vs baseline: 2.4599x; 1.4873x over previous
#include <cuda_runtime.h>
#include <cuda_bf16.h>
#include <math.h>
#include <cstdint>

// Problem constants
#define BSZ    2
#define CDIM   256
#define NDIM   16384      // 128*128
#define HDIM   128
#define WDIM   128
#define NKV    1024       // 32*32
#define NHEADS 8
#define HD     32
#define EPSBN  1e-5f
#define KSR    4096       // CDIM*4*4

typedef unsigned long long u64;
typedef unsigned int u32;
typedef unsigned short u16;

// ===================== f32x2 helpers (scalar k GEMM) ==========================
__device__ __forceinline__ u64 pack2(float lo, float hi) {
    u64 r; asm("mov.b64 %0, {%1, %2};" : "=l"(r) : "f"(lo), "f"(hi)); return r;
}
__device__ __forceinline__ u64 fma2(u64 a, u64 b, u64 c) {
    u64 d; asm("fma.rn.f32x2 %0, %1, %2, %3;" : "=l"(d) : "l"(a), "l"(b), "l"(c)); return d;
}
__device__ __forceinline__ float2 unpack2(u64 a) {
    float lo, hi; asm("mov.b64 {%0, %1}, %2;" : "=f"(lo), "=f"(hi) : "l"(a));
    return make_float2(lo, hi);
}

// ===================== mma/ldmatrix helpers ===================================
__device__ __forceinline__ u32 smem_u32(const void* p) {
    u32 a; asm("{ .reg .u64 t; cvta.to.shared.u64 t, %1; cvt.u32.u64 %0, t; }"
               : "=r"(a) : "l"(p)); return a;
}
__device__ __forceinline__ void ldm_x4(u32 r[4], u32 addr) {
    asm volatile("ldmatrix.sync.aligned.m8n8.x4.shared.b16 {%0,%1,%2,%3}, [%4];"
                 : "=r"(r[0]), "=r"(r[1]), "=r"(r[2]), "=r"(r[3]) : "r"(addr));
}
__device__ __forceinline__ void mma_z(float& c0, float& c1, float& c2, float& c3,
                                      u32 a0, u32 a1, u32 a2, u32 a3,
                                      u32 b0, u32 b1) {
    asm volatile("mma.sync.aligned.m16n8k16.row.col.f32.bf16.bf16.f32 "
                 "{%0,%1,%2,%3}, {%4,%5,%6,%7}, {%8,%9}, {%10,%10,%10,%10};"
                 : "=f"(c0), "=f"(c1), "=f"(c2), "=f"(c3)
                 : "r"(a0), "r"(a1), "r"(a2), "r"(a3), "r"(b0), "r"(b1), "f"(0.0f));
}
__device__ __forceinline__ void mma_a(float& c0, float& c1, float& c2, float& c3,
                                      u32 a0, u32 a1, u32 a2, u32 a3,
                                      u32 b0, u32 b1) {
    asm volatile("mma.sync.aligned.m16n8k16.row.col.f32.bf16.bf16.f32 "
                 "{%0,%1,%2,%3}, {%4,%5,%6,%7}, {%8,%9}, {%0,%1,%2,%3};"
                 : "+f"(c0), "+f"(c1), "+f"(c2), "+f"(c3)
                 : "r"(a0), "r"(a1), "r"(a2), "r"(a3), "r"(b0), "r"(b1));
}
__device__ __forceinline__ u32 sw128(u32 b) { return b ^ ((b >> 3) & 0x70); }

// ===================== bf16 split helpers =====================================
__device__ __forceinline__ void split1(float v, u16& h, u16& l) {
    __nv_bfloat16 hb = __float2bfloat16_rn(v);
    float hf = __bfloat162float(hb);
    __nv_bfloat16 lb = __float2bfloat16_rn(v - hf);
    h = __bfloat16_as_ushort(hb); l = __bfloat16_as_ushort(lb);
}
__device__ __forceinline__ void split4(float4 v, u64& hi, u64& lo) {
    u16 h0,l0,h1,l1,h2,l2,h3,l3;
    split1(v.x,h0,l0); split1(v.y,h1,l1); split1(v.z,h2,l2); split1(v.w,h3,l3);
    hi = (u64)h0 | ((u64)h1<<16) | ((u64)h2<<32) | ((u64)h3<<48);
    lo = (u64)l0 | ((u64)l1<<16) | ((u64)l2<<32) | ((u64)l3<<48);
}
__device__ __forceinline__ void split2u32(float v0, float v1, u32& hi, u32& lo) {
    u16 h0,l0,h1,l1; split1(v0,h0,l0); split1(v1,h1,l1);
    hi = (u32)h0 | ((u32)h1<<16); lo = (u32)l0 | ((u32)l1<<16);
}

// ===================== scratch ================================================
__device__ __align__(16) u16  g_qbf [BSZ * NHEADS * NDIM * 64];
__device__ __align__(16) u16  g_kbf [BSZ * NHEADS * NKV  * 64];
__device__ __align__(16) u16  g_Xt  [BSZ * NDIM * 512];    // [b,n][hi 256|lo 256]
__device__ __align__(16) u16  g_Xp  [BSZ * NKV * 8192];    // [b,m][hi 4096|lo 4096]
__device__ __align__(16) u16  g_wqs [CDIM * 512];
__device__ __align__(16) u16  g_wsrs[CDIM * 8192];
__device__ float g_part[16 * CDIM * NKV];                  // split-K partials
__device__ float g_xr  [BSZ * CDIM * NKV];
__device__ float g_attn[BSZ * NHEADS * NDIM];
__device__ float g_S   [BSZ * NDIM];
__device__ float g_v   [BSZ * CDIM];
__device__ float g_alpha[BSZ * CDIM];
__device__ float g_bias [CDIM];

// ===================== prep: W fp32 -> split bf16 rows ========================
__global__ __launch_bounds__(256) void convert_w(
    const float* __restrict__ W, u16* __restrict__ out, int K) {
    const int idx = blockIdx.x * 256 + threadIdx.x;
    const int fl = idx * 4;
    const int row = fl / K;
    const int k = fl - row * K;
    float4 v = *(const float4*)&W[fl];
    u64 hi, lo; split4(v, hi, lo);
    u16* o = out + (size_t)row * 2 * K + k;
    *(u64*)o = hi;
    *(u64*)(o + K) = lo;
}

// ===================== prep: x -> Xt (transpose + split) ======================
__global__ __launch_bounds__(256) void transpose_split_x(
    const float* __restrict__ x, u16* __restrict__ Xt) {
    __shared__ float s[64][136];
    const int n0 = blockIdx.x * 64;
    const int chf = blockIdx.y;       // c half (128 each)
    const int b = blockIdx.z;
    const int tid = threadIdx.x;
    const int cl = tid & 127, jh = tid >> 7;
    const float* xp = x + ((size_t)(b * CDIM + chf * 128 + cl)) * NDIM + n0 + jh * 32;
    #pragma unroll
    for (int j4 = 0; j4 < 8; ++j4) {
        float4 v = *(const float4*)&xp[j4 * 4];
        const int j = jh * 32 + j4 * 4;
        s[j + 0][cl] = v.x; s[j + 1][cl] = v.y;
        s[j + 2][cl] = v.z; s[j + 3][cl] = v.w;
    }
    __syncthreads();
    const int n = tid >> 2, cq = tid & 3;
    u16* orow = Xt + ((size_t)(b * NDIM + n0 + n)) * 512 + chf * 128;
    #pragma unroll
    for (int i = 0; i < 8; ++i) {
        const int c0 = (cq + i * 4) * 4;
        float4 v = *(float4*)&s[n][c0];
        u64 hi, lo; split4(v, hi, lo);
        *(u64*)(orow + c0) = hi;
        *(u64*)(orow + 256 + c0) = lo;
    }
}

// ===================== prep: x -> Xp (patch gather + split) ===================
__global__ __launch_bounds__(256) void gather_patches(
    const float* __restrict__ x, u16* __restrict__ Xp) {
    const int idx = blockIdx.x * 256 + threadIdx.x;   // 524288 total
    const int b = idx >> 18;
    const int rem = idx & 262143;
    const int c = rem >> 10;
    const int hh = (rem >> 5) & 31;
    const int ww = rem & 31;
    const float* xc = x + ((size_t)(b * CDIM + c)) * NDIM;
    u16* orow = Xp + ((size_t)(b * NKV + hh * 32 + ww)) * 8192 + c * 16;
    #pragma unroll
    for (int p = 0; p < 4; ++p) {
        float4 v = *(const float4*)&xc[(hh * 4 + p) * WDIM + ww * 4];
        u64 hi, lo; split4(v, hi, lo);
        *(u64*)(orow + p * 4) = hi;
        *(u64*)(orow + 4096 + p * 4) = lo;
    }
}

// ===================== q GEMM on mma.sync =====================================
// A = Xt rows (M = n), B = Wq split rows (N = o), K = 256 (4 chunks of 64).
__global__ __launch_bounds__(256, 1) void qgemm_mma(
    const u16* __restrict__ Xt, const u16* __restrict__ Wq,
    u16* __restrict__ qbf) {
    extern __shared__ char sm[];
    const u32 sb = smem_u32(sm);
    const int tid = threadIdx.x;
    const int l = tid & 31, wid = tid >> 5;
    const int wm = wid & 3, wo = wid >> 2;
    const int blkn = blockIdx.x, blko = blockIdx.y, bb = blockIdx.z;

    const u16* XtB = Xt + (size_t)(bb * NDIM + blkn * 128) * 512;
    const u16* WqB = Wq + (size_t)(blko * 128) * 512;

    float acc[2][8][4];
    #pragma unroll
    for (int a = 0; a < 2; ++a)
        #pragma unroll
        for (int c = 0; c < 8; ++c)
            #pragma unroll
            for (int d = 0; d < 4; ++d) acc[a][c][d] = 0.f;

    u32 rowA[2], rowB[4];
    #pragma unroll
    for (int mt = 0; mt < 2; ++mt)
        rowA[mt] = (u32)(wm * 32 + mt * 16 + (l & 7) + (l & 8)) * 128;
    #pragma unroll
    for (int g = 0; g < 4; ++g)
        rowB[g] = (u32)(wo * 64 + g * 16 + (l & 7) + ((l & 16) >> 1)) * 128;

    for (int kc = 0; kc < 4; ++kc) {
        for (int i = tid; i < 1024; i += 256) {
            const int row = i >> 3, ch = i & 7;
            const u32 dst = sw128((u32)(row * 128 + ch * 16));
            const size_t off = (size_t)row * 512 + kc * 64 + ch * 8;
            *(uint4*)(sm + dst)         = *(const uint4*)(XtB + off);
            *(uint4*)(sm + 16384 + dst) = *(const uint4*)(XtB + off + 256);
            *(uint4*)(sm + 32768 + dst) = *(const uint4*)(WqB + off);
            *(uint4*)(sm + 49152 + dst) = *(const uint4*)(WqB + off + 256);
        }
        __syncthreads();
        #pragma unroll
        for (int s = 0; s < 4; ++s) {
            const u32 cA = ((u32)((2 * s + ((l >> 4) & 1)) ^ (l & 7))) << 4;
            const u32 cB = ((u32)((2 * s + ((l >> 3) & 1)) ^ (l & 7))) << 4;
            u32 ah[2][4], al[2][4], bhf[4][4], blf[4][4];
            #pragma unroll
            for (int mt = 0; mt < 2; ++mt) {
                ldm_x4(ah[mt], sb + rowA[mt] + cA);
                ldm_x4(al[mt], sb + 16384 + rowA[mt] + cA);
            }
            #pragma unroll
            for (int g = 0; g < 4; ++g) {
                ldm_x4(bhf[g], sb + 32768 + rowB[g] + cB);
                ldm_x4(blf[g], sb + 49152 + rowB[g] + cB);
            }
            #pragma unroll
            for (int mt = 0; mt < 2; ++mt)
                #pragma unroll
                for (int g = 0; g < 4; ++g)
                    #pragma unroll
                    for (int hf = 0; hf < 2; ++hf) {
                        float* A4 = acc[mt][g * 2 + hf];
                        mma_a(A4[0], A4[1], A4[2], A4[3],
                              ah[mt][0], ah[mt][1], ah[mt][2], ah[mt][3],
                              bhf[g][2 * hf], bhf[g][2 * hf + 1]);
                        mma_a(A4[0], A4[1], A4[2], A4[3],
                              ah[mt][0], ah[mt][1], ah[mt][2], ah[mt][3],
                              blf[g][2 * hf], blf[g][2 * hf + 1]);
                        mma_a(A4[0], A4[1], A4[2], A4[3],
                              al[mt][0], al[mt][1], al[mt][2], al[mt][3],
                              bhf[g][2 * hf], bhf[g][2 * hf + 1]);
                    }
        }
        __syncthreads();
    }

    // epilogue: (row n, col o) -> qbf[bh][n][d hi | 32+d lo]
    #pragma unroll
    for (int mt = 0; mt < 2; ++mt) {
        const int n0g = blkn * 128 + wm * 32 + mt * 16 + (l >> 2);
        #pragma unroll
        for (int nt = 0; nt < 8; ++nt) {
            const int o = blko * 128 + wo * 64 + nt * 8 + 2 * (l & 3);
            const int bh_ = bb * NHEADS + (o >> 5);
            const int d = o & 31;
            u16* base = qbf + ((size_t)bh_ * NDIM + n0g) * 64 + d;
            u32 hi0, lo0; split2u32(acc[mt][nt][0], acc[mt][nt][1], hi0, lo0);
            *(u32*)base = hi0; *(u32*)(base + 32) = lo0;
            u32 hi1, lo1; split2u32(acc[mt][nt][2], acc[mt][nt][3], hi1, lo1);
            u16* base2 = base + 8 * 64;
            *(u32*)base2 = hi1; *(u32*)(base2 + 32) = lo1;
        }
    }
}

// ===================== conv GEMM on mma.sync (split-K=8) ======================
// A = Wsr rows (M = o), B = Xp rows (N = m), K part = 512 (8 chunks of 64).
__global__ __launch_bounds__(256, 1) void convgemm_mma(
    const u16* __restrict__ Wsr, const u16* __restrict__ Xp,
    float* __restrict__ part) {
    extern __shared__ char sm[];
    const u32 sb = smem_u32(sm);
    const int tid = threadIdx.x;
    const int l = tid & 31, wid = tid >> 5;
    const int wm = wid & 3, wo = wid >> 2;
    const int blkm = blockIdx.x, blko = blockIdx.y;
    const int zz = blockIdx.z;          // ks*2 + b
    const int bb = zz & 1, ks = zz >> 1;

    const u16* AB = Wsr + (size_t)(blko * 128) * 8192;
    const u16* BB = Xp + (size_t)(bb * NKV + blkm * 128) * 8192;

    float acc[2][8][4];
    #pragma unroll
    for (int a = 0; a < 2; ++a)
        #pragma unroll
        for (int c = 0; c < 8; ++c)
            #pragma unroll
            for (int d = 0; d < 4; ++d) acc[a][c][d] = 0.f;

    u32 rowA[2], rowB[4];
    #pragma unroll
    for (int mt = 0; mt < 2; ++mt)
        rowA[mt] = (u32)(wm * 32 + mt * 16 + (l & 7) + (l & 8)) * 128;
    #pragma unroll
    for (int g = 0; g < 4; ++g)
        rowB[g] = (u32)(wo * 64 + g * 16 + (l & 7) + ((l & 16) >> 1)) * 128;

    for (int kcl = 0; kcl < 8; ++kcl) {
        const int kcg = ks * 8 + kcl;
        for (int i = tid; i < 1024; i += 256) {
            const int row = i >> 3, ch = i & 7;
            const u32 dst = sw128((u32)(row * 128 + ch * 16));
            const size_t off = (size_t)row * 8192 + kcg * 64 + ch * 8;
            *(uint4*)(sm + dst)         = *(const uint4*)(AB + off);
            *(uint4*)(sm + 16384 + dst) = *(const uint4*)(AB + off + 4096);
            *(uint4*)(sm + 32768 + dst) = *(const uint4*)(BB + off);
            *(uint4*)(sm + 49152 + dst) = *(const uint4*)(BB + off + 4096);
        }
        __syncthreads();
        #pragma unroll
        for (int s = 0; s < 4; ++s) {
            const u32 cA = ((u32)((2 * s + ((l >> 4) & 1)) ^ (l & 7))) << 4;
            const u32 cB = ((u32)((2 * s + ((l >> 3) & 1)) ^ (l & 7))) << 4;
            u32 ah[2][4], al[2][4], bhf[4][4], blf[4][4];
            #pragma unroll
            for (int mt = 0; mt < 2; ++mt) {
                ldm_x4(ah[mt], sb + rowA[mt] + cA);
                ldm_x4(al[mt], sb + 16384 + rowA[mt] + cA);
            }
            #pragma unroll
            for (int g = 0; g < 4; ++g) {
                ldm_x4(bhf[g], sb + 32768 + rowB[g] + cB);
                ldm_x4(blf[g], sb + 49152 + rowB[g] + cB);
            }
            #pragma unroll
            for (int mt = 0; mt < 2; ++mt)
                #pragma unroll
                for (int g = 0; g < 4; ++g)
                    #pragma unroll
                    for (int hf = 0; hf < 2; ++hf) {
                        float* A4 = acc[mt][g * 2 + hf];
                        mma_a(A4[0], A4[1], A4[2], A4[3],
                              ah[mt][0], ah[mt][1], ah[mt][2], ah[mt][3],
                              bhf[g][2 * hf], bhf[g][2 * hf + 1]);
                        mma_a(A4[0], A4[1], A4[2], A4[3],
                              ah[mt][0], ah[mt][1], ah[mt][2], ah[mt][3],
                              blf[g][2 * hf], blf[g][2 * hf + 1]);
                        mma_a(A4[0], A4[1], A4[2], A4[3],
                              al[mt][0], al[mt][1], al[mt][2], al[mt][3],
                              bhf[g][2 * hf], bhf[g][2 * hf + 1]);
                    }
        }
        __syncthreads();
    }

    // epilogue: (row o, col m) fp32 partials
    #pragma unroll
    for (int mt = 0; mt < 2; ++mt) {
        const int o = blko * 128 + wm * 32 + mt * 16 + (l >> 2);
        #pragma unroll
        for (int nt = 0; nt < 8; ++nt) {
            const int m = blkm * 128 + wo * 64 + nt * 8 + 2 * (l & 3);
            float* dst = part + ((size_t)zz * CDIM + o) * NKV + m;
            *(float2*)dst = make_float2(acc[mt][nt][0], acc[mt][nt][1]);
            *(float2*)(dst + 8 * NKV) = make_float2(acc[mt][nt][2], acc[mt][nt][3]);
        }
    }
}

// ===================== conv reduce + BN =======================================
__global__ __launch_bounds__(256) void conv_reduce_bn(
    const float* __restrict__ part,
    const float* __restrict__ gam, const float* __restrict__ bet,
    const float* __restrict__ mu,  const float* __restrict__ var,
    float* __restrict__ xr) {
    const int idx = blockIdx.x * 256 + threadIdx.x;   // over 2*256*1024/4
    const int fl = idx * 4;
    const int b = fl >> 18;
    const int o = (fl >> 10) & 255;
    const int m = fl & 1023;
    float4 s = make_float4(0.f, 0.f, 0.f, 0.f);
    #pragma unroll
    for (int ks = 0; ks < 8; ++ks) {
        const float4 p = *(const float4*)&part[((size_t)(ks * 2 + b) * CDIM + o) * NKV + m];
        s.x += p.x; s.y += p.y; s.z += p.z; s.w += p.w;
    }
    const float inv = gam[o] * rsqrtf(var[o] + EPSBN);
    const float mb = mu[o], be = bet[o];
    float4 r = make_float4((s.x - mb) * inv + be, (s.y - mb) * inv + be,
                           (s.z - mb) * inv + be, (s.w - mb) * inv + be);
    *(float4*)&xr[((size_t)(b * CDIM + o)) * NKV + m] = r;
}

// ===================== k GEMM (scalar f32x2, split-bf16 epilogue) =============
__global__ __launch_bounds__(256) void gemm_split(
    const float* __restrict__ W, const float* __restrict__ X,
    u16* __restrict__ Out, int Ncol) {
    __shared__ float As[16][64];
    __shared__ float Bs[16][64];
    const int b  = blockIdx.z;
    const float* Xb = X + (size_t)b * CDIM * Ncol;
    const int bm = blockIdx.y * 64;
    const int bn = blockIdx.x * 64;
    const int tid = threadIdx.x;
    const int tm = tid >> 4, tn = tid & 15;

    u64 acc[4][2] = {};
    for (int k0 = 0; k0 < CDIM; k0 += 16) {
        const int ar = tid >> 2, ac = (tid & 3) * 4;
        float4 a4 = *(const float4*)&W[(size_t)(bm + ar) * CDIM + k0 + ac];
        As[ac + 0][ar] = a4.x; As[ac + 1][ar] = a4.y;
        As[ac + 2][ar] = a4.z; As[ac + 3][ar] = a4.w;
        const int br = tid >> 4, bc = (tid & 15) * 4;
        *(float4*)&Bs[br][bc] = *(const float4*)&Xb[(size_t)(k0 + br) * Ncol + bn + bc];
        __syncthreads();
        #pragma unroll
        for (int kk = 0; kk < 16; ++kk) {
            float4 av = *(const float4*)&As[kk][tm * 4];
            ulonglong2 bv = *(const ulonglong2*)&Bs[kk][tn * 4];
            u64 a0 = pack2(av.x, av.x), a1 = pack2(av.y, av.y);
            u64 a2 = pack2(av.z, av.z), a3 = pack2(av.w, av.w);
            acc[0][0] = fma2(a0, bv.x, acc[0][0]); acc[0][1] = fma2(a0, bv.y, acc[0][1]);
            acc[1][0] = fma2(a1, bv.x, acc[1][0]); acc[1][1] = fma2(a1, bv.y, acc[1][1]);
            acc[2][0] = fma2(a2, bv.x, acc[2][0]); acc[2][1] = fma2(a2, bv.y, acc[2][1]);
            acc[3][0] = fma2(a3, bv.x, acc[3][0]); acc[3][1] = fma2(a3, bv.y, acc[3][1]);
        }
        __syncthreads();
    }
    const int o0 = bm + tm * 4;
    const int d0 = o0 & 31;
    const int bh = b * NHEADS + (o0 >> 5);
    #pragma unroll
    for (int j = 0; j < 4; ++j) {
        const int col = bn + tn * 4 + j;
        u64 hi_pack = 0, lo_pack = 0;
        #pragma unroll
        for (int i = 0; i < 4; ++i) {
            float2 f = unpack2(acc[i][j >> 1]);
            float v = (j & 1) ? f.y : f.x;
            u16 h, lw; split1(v, h, lw);
            hi_pack |= (u64)h << (16 * i);
            lo_pack |= (u64)lw << (16 * i);
        }
        u16* base = Out + ((size_t)bh * Ncol + col) * 64 + d0;
        *(u64*)base        = hi_pack;
        *(u64*)(base + 32) = lo_pack;
    }
}

// ---------------- v = mean_n x ------------------------------------------------
__global__ __launch_bounds__(256) void mean_v(const float* __restrict__ x,
                                              float* __restrict__ v) {
    const int bc = blockIdx.x;
    const float* xp = x + (size_t)bc * NDIM;
    float s = 0.f;
    for (int i = threadIdx.x * 4; i < NDIM; i += 256 * 4) {
        float4 t = *(const float4*)&xp[i];
        s += (t.x + t.y) + (t.z + t.w);
    }
    __shared__ float red[256];
    red[threadIdx.x] = s;
    __syncthreads();
    for (int st = 128; st > 0; st >>= 1) {
        if (threadIdx.x < st) red[threadIdx.x] += red[threadIdx.x + st];
        __syncthreads();
    }
    if (threadIdx.x == 0) v[bc] = red[0] * (1.0f / NDIM);
}

// ---------------- alpha/bias --------------------------------------------------
__global__ __launch_bounds__(256) void alpha_kernel(
    const float* __restrict__ wproj, const float* __restrict__ v,
    const float* __restrict__ gam, const float* __restrict__ bet,
    const float* __restrict__ mu,  const float* __restrict__ var,
    float* __restrict__ alpha, float* __restrict__ bias) {
    const int b = blockIdx.x;
    const int o = threadIdx.x;
    __shared__ float vs[CDIM];
    vs[o] = v[b * CDIM + o];
    __syncthreads();
    float p = 0.f;
    const float* wr = wproj + (size_t)o * CDIM;
    #pragma unroll 8
    for (int c = 0; c < CDIM; ++c) p = fmaf(wr[c], vs[c], p);
    const float inv = gam[o] * rsqrtf(var[o] + EPSBN);
    alpha[b * CDIM + o] = p * inv;
    if (b == 0) bias[o] = bet[o] - mu[o] * inv;
}

// ===================== mma.sync attention =====================================
#define SM_QOFF 131072
#define SM_TOT  147456
#define NTILES  16

__global__ __launch_bounds__(128, 1)
void attn_mma(const u16* __restrict__ qbf, const u16* __restrict__ kbf,
              float* __restrict__ attn) {
    extern __shared__ char smem[];
    const u32 sb  = smem_u32(smem);
    const u32 ksb = sb;
    const u32 qsb = sb + SM_QOFF;
    const int tid = threadIdx.x;
    const int wid = tid >> 5, l = tid & 31;
    const int bh  = blockIdx.x >> 3;
    const int seg = blockIdx.x & 7;

    {
        const uint4* ksrc = (const uint4*)(kbf + (size_t)bh * NKV * 64);
        for (int idx = tid; idx < NKV * 8; idx += 128) {
            const int row = idx >> 3, c = idx & 7;
            *(uint4*)(smem + sw128(row * 128 + c * 16)) = ksrc[idx];
        }
    }
    __syncthreads();

    const int brow = (l & 7) + ((l & 16) >> 1);
    u32 baddr[4];
    #pragma unroll
    for (int s = 0; s < 4; ++s)
        baddr[s] = ksb + brow * 128 + ((u32)((2 * s + ((l >> 3) & 1)) ^ (l & 7)) << 4);

    const int arow = (l & 7) + (l & 8);
    u32 aaddr[4];
    #pragma unroll
    for (int s = 0; s < 4; ++s)
        aaddr[s] = qsb + arow * 128 + ((u32)((2 * s + ((l >> 4) & 1)) ^ (l & 7)) << 4);

    const float scale = 0.17677669529663687f;
    float* ob = attn + (size_t)bh * NDIM;

    for (int t = 0; t < NTILES; ++t) {
        const int n_base = (seg * NTILES + t) * 128;
        {
            const uint4* qsrc = (const uint4*)(qbf + ((size_t)bh * NDIM + n_base) * 64);
            #pragma unroll
            for (int j = 0; j < 8; ++j)
                *(uint4*)(smem + SM_QOFF + sw128(tid * 128 + j * 16)) = qsrc[(size_t)tid * 8 + j];
        }
        __syncwarp();

        u32 a[2][4][4];
        #pragma unroll
        for (int mt = 0; mt < 2; ++mt) {
            const u32 roff = (u32)(wid * 32 + mt * 16) * 128;
            #pragma unroll
            for (int s = 0; s < 4; ++s)
                ldm_x4(a[mt][s], aaddr[s] + roff);
        }
        __syncwarp();

        float rmax[2][2] = {{-INFINITY, -INFINITY}, {-INFINITY, -INFINITY}};
        for (int kv = 0; kv < 64; ++kv) {
            const u32 off = (u32)kv * 2048;
            u32 bh0[4], bh1[4], bl0[4], bl1[4];
            ldm_x4(bh0, baddr[0] + off);
            ldm_x4(bh1, baddr[1] + off);
            ldm_x4(bl0, baddr[2] + off);
            ldm_x4(bl1, baddr[3] + off);
            #pragma unroll
            for (int mt = 0; mt < 2; ++mt) {
                #pragma unroll
                for (int g = 0; g < 2; ++g) {
                    float c0, c1, c2, c3;
                    mma_z(c0, c1, c2, c3, a[mt][0][0], a[mt][0][1], a[mt][0][2], a[mt][0][3],
                          bh0[2 * g], bh0[2 * g + 1]);
                    mma_a(c0, c1, c2, c3, a[mt][1][0], a[mt][1][1], a[mt][1][2], a[mt][1][3],
                          bh1[2 * g], bh1[2 * g + 1]);
                    mma_a(c0, c1, c2, c3, a[mt][0][0], a[mt][0][1], a[mt][0][2], a[mt][0][3],
                          bl0[2 * g], bl0[2 * g + 1]);
                    mma_a(c0, c1, c2, c3, a[mt][1][0], a[mt][1][1], a[mt][1][2], a[mt][1][3],
                          bl1[2 * g], bl1[2 * g + 1]);
                    mma_a(c0, c1, c2, c3, a[mt][2][0], a[mt][2][1], a[mt][2][2], a[mt][2][3],
                          bh0[2 * g], bh0[2 * g + 1]);
                    mma_a(c0, c1, c2, c3, a[mt][3][0], a[mt][3][1], a[mt][3][2], a[mt][3][3],
                          bh1[2 * g], bh1[2 * g + 1]);
                    rmax[mt][0] = fmaxf(rmax[mt][0], fmaxf(c0, c1));
                    rmax[mt][1] = fmaxf(rmax[mt][1], fmaxf(c2, c3));
                }
            }
        }
        #pragma unroll
        for (int mt = 0; mt < 2; ++mt)
            #pragma unroll
            for (int rr = 0; rr < 2; ++rr) {
                float v = rmax[mt][rr];
                v = fmaxf(v, __shfl_xor_sync(0xffffffffu, v, 1));
                v = fmaxf(v, __shfl_xor_sync(0xffffffffu, v, 2));
                rmax[mt][rr] = v;
            }
        if ((l & 3) == 0) {
            const int rbase = n_base + wid * 32;
            #pragma unroll
            for (int mt = 0; mt < 2; ++mt) {
                ob[rbase + mt * 16 + (l >> 2) + 0] = rmax[mt][0] * scale;
                ob[rbase + mt * 16 + (l >> 2) + 8] = rmax[mt][1] * scale;
            }
        }
        __syncwarp();
    }
}

// ---------------- S[b][n] = sum_h attn ----------------------------------------
__global__ __launch_bounds__(256) void reduce_attn(const float* __restrict__ attn,
                                                   float* __restrict__ S) {
    const int idx = blockIdx.x * 256 + threadIdx.x;
    const int b = idx >> 14, n = idx & (NDIM - 1);
    float s = 0.f;
    #pragma unroll
    for (int h = 0; h < NHEADS; ++h)
        s += attn[((size_t)b * NHEADS + h) * NDIM + n];
    S[idx] = s;
}

// ---------------- out = alpha*S + bias -----------------------------------------
__global__ __launch_bounds__(256) void final_kernel(
    const float* __restrict__ S, const float* __restrict__ alpha,
    const float* __restrict__ bias, float* __restrict__ out) {
    const size_t t = (size_t)blockIdx.x * 256 + threadIdx.x;
    const size_t idx4 = t * 4;
    const int bo = (int)(idx4 >> 14);
    const int n  = (int)(idx4 & (NDIM - 1));
    const int b  = bo >> 8, o = bo & 255;
    const float a  = alpha[bo];
    const float bi = bias[o];
    float4 s = *(const float4*)&S[(size_t)b * NDIM + n];
    float4 r;
    r.x = fmaf(a, s.x, bi); r.y = fmaf(a, s.y, bi);
    r.z = fmaf(a, s.z, bi); r.w = fmaf(a, s.w, bi);
    *(float4*)&out[idx4] = r;
}

// ===================== launch ==================================================
extern "C" void kernel_launch(void* const* d_in, const int* in_sizes, int n_in,
                              void* d_out, int out_size) {
    const float* x      = (const float*)d_in[0];
    const float* w_q    = (const float*)d_in[1];
    const float* w_k    = (const float*)d_in[2];
    const float* w_sr   = (const float*)d_in[3];
    const float* sr_g   = (const float*)d_in[4];
    const float* sr_b   = (const float*)d_in[5];
    const float* sr_m   = (const float*)d_in[6];
    const float* sr_v   = (const float*)d_in[7];
    const float* w_proj = (const float*)d_in[8];
    const float* pj_g   = (const float*)d_in[9];
    const float* pj_b   = (const float*)d_in[10];
    const float* pj_m   = (const float*)d_in[11];
    const float* pj_v   = (const float*)d_in[12];
    float* out = (float*)d_out;

    u16 *qbf, *kbf, *Xt, *Xp, *wqs, *wsrs;
    float *part, *xr, *attn, *S, *v, *alpha, *bias;
    cudaGetSymbolAddress((void**)&qbf,   g_qbf);
    cudaGetSymbolAddress((void**)&kbf,   g_kbf);
    cudaGetSymbolAddress((void**)&Xt,    g_Xt);
    cudaGetSymbolAddress((void**)&Xp,    g_Xp);
    cudaGetSymbolAddress((void**)&wqs,   g_wqs);
    cudaGetSymbolAddress((void**)&wsrs,  g_wsrs);
    cudaGetSymbolAddress((void**)&part,  g_part);
    cudaGetSymbolAddress((void**)&xr,    g_xr);
    cudaGetSymbolAddress((void**)&attn,  g_attn);
    cudaGetSymbolAddress((void**)&S,     g_S);
    cudaGetSymbolAddress((void**)&v,     g_v);
    cudaGetSymbolAddress((void**)&alpha, g_alpha);
    cudaGetSymbolAddress((void**)&bias,  g_bias);

    cudaFuncSetAttribute(attn_mma, cudaFuncAttributeMaxDynamicSharedMemorySize, SM_TOT);
    cudaFuncSetAttribute(qgemm_mma, cudaFuncAttributeMaxDynamicSharedMemorySize, 65536);
    cudaFuncSetAttribute(convgemm_mma, cudaFuncAttributeMaxDynamicSharedMemorySize, 65536);

    // prep: weights + x layouts (split bf16)
    convert_w<<<64, 256>>>(w_q, wqs, 256);
    convert_w<<<1024, 256>>>(w_sr, wsrs, 4096);
    transpose_split_x<<<dim3(256, 2, 2), 256>>>(x, Xt);
    gather_patches<<<2048, 256>>>(x, Xp);
    // q = w_q @ x  (tensor cores)
    qgemm_mma<<<dim3(128, 2, 2), 256, 65536>>>(Xt, wqs, qbf);
    // xr = BN(conv_sr(x))  (tensor cores, split-K)
    convgemm_mma<<<dim3(8, 2, 16), 256, 65536>>>(wsrs, Xp, part);
    conv_reduce_bn<<<512, 256>>>(part, sr_g, sr_b, sr_m, sr_v, xr);
    // k = w_k @ xr (scalar, small)
    gemm_split<<<dim3(NKV / 64, CDIM / 64, BSZ), 256>>>(w_k, xr, kbf, NKV);
    // v, alpha
    mean_v<<<BSZ * CDIM, 256>>>(x, v);
    alpha_kernel<<<BSZ, CDIM>>>(w_proj, v, pj_g, pj_b, pj_m, pj_v, alpha, bias);
    // attention rowmax (tensor cores)
    attn_mma<<<128, 128, SM_TOT>>>(qbf, kbf, attn);
    // tail
    reduce_attn<<<BSZ * NDIM / 256, 256>>>(attn, S);
    final_kernel<<<(BSZ * CDIM * NDIM / 4) / 256, 256>>>(S, alpha, bias, out);
}

// round 6
// speedup vs baseline: 2.5555x; 1.0388x over previous
#include <cuda_runtime.h>
#include <cuda_bf16.h>
#include <math.h>
#include <cstdint>

// Problem constants
#define BSZ    2
#define CDIM   256
#define NDIM   16384      // 128*128
#define HDIM   128
#define WDIM   128
#define NKV    1024       // 32*32
#define NHEADS 8
#define HD     32
#define EPSBN  1e-5f
#define KSR    4096       // CDIM*4*4

typedef unsigned long long u64;
typedef unsigned int u32;
typedef unsigned short u16;

// ===================== f32x2 helpers (scalar k GEMM) ==========================
__device__ __forceinline__ u64 pack2(float lo, float hi) {
    u64 r; asm("mov.b64 %0, {%1, %2};" : "=l"(r) : "f"(lo), "f"(hi)); return r;
}
__device__ __forceinline__ u64 fma2(u64 a, u64 b, u64 c) {
    u64 d; asm("fma.rn.f32x2 %0, %1, %2, %3;" : "=l"(d) : "l"(a), "l"(b), "l"(c)); return d;
}
__device__ __forceinline__ float2 unpack2(u64 a) {
    float lo, hi; asm("mov.b64 {%0, %1}, %2;" : "=f"(lo), "=f"(hi) : "l"(a));
    return make_float2(lo, hi);
}

// ===================== mma/ldmatrix helpers ===================================
__device__ __forceinline__ u32 smem_u32(const void* p) {
    u32 a; asm("{ .reg .u64 t; cvta.to.shared.u64 t, %1; cvt.u32.u64 %0, t; }"
               : "=r"(a) : "l"(p)); return a;
}
__device__ __forceinline__ void ldm_x4(u32 r[4], u32 addr) {
    asm volatile("ldmatrix.sync.aligned.m8n8.x4.shared.b16 {%0,%1,%2,%3}, [%4];"
                 : "=r"(r[0]), "=r"(r[1]), "=r"(r[2]), "=r"(r[3]) : "r"(addr));
}
__device__ __forceinline__ void mma_z(float& c0, float& c1, float& c2, float& c3,
                                      u32 a0, u32 a1, u32 a2, u32 a3,
                                      u32 b0, u32 b1) {
    asm volatile("mma.sync.aligned.m16n8k16.row.col.f32.bf16.bf16.f32 "
                 "{%0,%1,%2,%3}, {%4,%5,%6,%7}, {%8,%9}, {%10,%10,%10,%10};"
                 : "=f"(c0), "=f"(c1), "=f"(c2), "=f"(c3)
                 : "r"(a0), "r"(a1), "r"(a2), "r"(a3), "r"(b0), "r"(b1), "f"(0.0f));
}
__device__ __forceinline__ void mma_a(float& c0, float& c1, float& c2, float& c3,
                                      u32 a0, u32 a1, u32 a2, u32 a3,
                                      u32 b0, u32 b1) {
    asm volatile("mma.sync.aligned.m16n8k16.row.col.f32.bf16.bf16.f32 "
                 "{%0,%1,%2,%3}, {%4,%5,%6,%7}, {%8,%9}, {%0,%1,%2,%3};"
                 : "+f"(c0), "+f"(c1), "+f"(c2), "+f"(c3)
                 : "r"(a0), "r"(a1), "r"(a2), "r"(a3), "r"(b0), "r"(b1));
}
__device__ __forceinline__ u32 sw128(u32 b) { return b ^ ((b >> 3) & 0x70); }

// ===================== bf16 split helpers =====================================
__device__ __forceinline__ void split1(float v, u16& h, u16& l) {
    __nv_bfloat16 hb = __float2bfloat16_rn(v);
    float hf = __bfloat162float(hb);
    __nv_bfloat16 lb = __float2bfloat16_rn(v - hf);
    h = __bfloat16_as_ushort(hb); l = __bfloat16_as_ushort(lb);
}
__device__ __forceinline__ void split4(float4 v, u64& hi, u64& lo) {
    u16 h0,l0,h1,l1,h2,l2,h3,l3;
    split1(v.x,h0,l0); split1(v.y,h1,l1); split1(v.z,h2,l2); split1(v.w,h3,l3);
    hi = (u64)h0 | ((u64)h1<<16) | ((u64)h2<<32) | ((u64)h3<<48);
    lo = (u64)l0 | ((u64)l1<<16) | ((u64)l2<<32) | ((u64)l3<<48);
}
__device__ __forceinline__ void split2u32(float v0, float v1, u32& hi, u32& lo) {
    u16 h0,l0,h1,l1; split1(v0,h0,l0); split1(v1,h1,l1);
    hi = (u32)h0 | ((u32)h1<<16); lo = (u32)l0 | ((u32)l1<<16);
}

// ===================== scratch ================================================
__device__ __align__(16) u16  g_qbf [BSZ * NHEADS * NDIM * 64];
__device__ __align__(16) u16  g_kbf [BSZ * NHEADS * NKV  * 64];
__device__ __align__(16) u16  g_Xt  [BSZ * NDIM * 512];    // [b,n][hi 256|lo 256]
__device__ __align__(16) u16  g_Xp  [BSZ * NKV * 8192];    // [b,m][hi 4096|lo 4096]
__device__ __align__(16) u16  g_wqs [CDIM * 512];
__device__ __align__(16) u16  g_wsrs[CDIM * 8192];
__device__ float g_part[16 * CDIM * NKV];                  // split-K partials
__device__ float g_xr  [BSZ * CDIM * NKV];
__device__ float g_attn[BSZ * NHEADS * NDIM];
__device__ float g_S   [BSZ * NDIM];
__device__ float g_v   [BSZ * CDIM];
__device__ float g_alpha[BSZ * CDIM];
__device__ float g_bias [CDIM];

// ===================== prep: W fp32 -> split bf16 rows ========================
__global__ __launch_bounds__(256) void convert_w(
    const float* __restrict__ W, u16* __restrict__ out, int K) {
    const int idx = blockIdx.x * 256 + threadIdx.x;
    const int fl = idx * 4;
    const int row = fl / K;
    const int k = fl - row * K;
    float4 v = *(const float4*)&W[fl];
    u64 hi, lo; split4(v, hi, lo);
    u16* o = out + (size_t)row * 2 * K + k;
    *(u64*)o = hi;
    *(u64*)(o + K) = lo;
}

// ===================== prep: x -> Xt (coalesced tile transpose + split) =======
// tile 64c x 64n; grid (N/64, C/64, B); 256 threads.
__global__ __launch_bounds__(256) void transpose_split_x(
    const float* __restrict__ x, u16* __restrict__ Xt) {
    __shared__ float s[64][65];
    const int n0 = blockIdx.x * 64;
    const int c0 = blockIdx.y * 64;
    const int b  = blockIdx.z;
    const int tid = threadIdx.x;
    // read coalesced along n
    #pragma unroll
    for (int i = 0; i < 4; ++i) {
        const int idx = i * 256 + tid;
        const int c_l = idx >> 4, nq = idx & 15;
        float4 v = *(const float4*)&x[((size_t)(b * CDIM + c0 + c_l)) * NDIM + n0 + nq * 4];
        s[c_l][nq * 4 + 0] = v.x; s[c_l][nq * 4 + 1] = v.y;
        s[c_l][nq * 4 + 2] = v.z; s[c_l][nq * 4 + 3] = v.w;
    }
    __syncthreads();
    // write split rows (n-major)
    const int n_l = tid >> 2, cq = tid & 3;
    u16* orow = Xt + ((size_t)(b * NDIM + n0 + n_l)) * 512 + c0;
    #pragma unroll
    for (int i = 0; i < 4; ++i) {
        const int c_loc = (cq + i * 4) * 4;
        float4 v = make_float4(s[c_loc][n_l], s[c_loc + 1][n_l],
                               s[c_loc + 2][n_l], s[c_loc + 3][n_l]);
        u64 hi, lo; split4(v, hi, lo);
        *(u64*)(orow + c_loc) = hi;
        *(u64*)(orow + 256 + c_loc) = lo;
    }
}

// ===================== prep: x -> Xp (smem-staged patch gather + split) =======
// block = (cchunk, hh, b); 32 c x 32 ww x 16 el; smem hi 32KB + lo 32KB.
__global__ __launch_bounds__(256) void gather_patches(
    const float* __restrict__ x, u16* __restrict__ Xp) {
    extern __shared__ char gsm[];   // [0,32768) hi, [32768,65536) lo
    const int cch = blockIdx.x;     // 0..7
    const int hh  = blockIdx.y;     // 0..31
    const int b   = blockIdx.z;
    const int tid = threadIdx.x;
    // read + split + swizzled smem store
    #pragma unroll
    for (int i = 0; i < 16; ++i) {
        const int idx = i * 256 + tid;
        const int c_l = idx >> 7;
        const int rem = idx & 127;
        const int p = rem >> 5, w4 = rem & 31;
        float4 v = *(const float4*)&x[((size_t)(b * CDIM + cch * 32 + c_l)) * NDIM
                                      + (hh * 4 + p) * WDIM + w4 * 4];
        u64 hi, lo; split4(v, hi, lo);
        const u32 off = (u32)(c_l * 32 + p * 8);
        const u32 phys = (off ^ ((u32)(w4 & 15) << 3)) + (u32)w4 * 1024;
        *(u64*)(gsm + phys) = hi;
        *(u64*)(gsm + 32768 + phys) = lo;
    }
    __syncthreads();
    // write coalesced: row ww, units j 0..127 per plane
    #pragma unroll
    for (int i = 0; i < 16; ++i) {
        const int idx = i * 256 + tid;
        const int ww = idx >> 7, j = idx & 127;
        const u32 phys = (((u32)j * 8) ^ ((u32)(ww & 15) << 3)) + (u32)ww * 1024;
        u16* dst = Xp + ((size_t)(b * NKV + hh * 32 + ww)) * 8192 + cch * 512 + j * 4;
        *(u64*)dst = *(const u64*)(gsm + phys);
        *(u64*)(dst + 4096) = *(const u64*)(gsm + 32768 + phys);
    }
}

// ===================== q GEMM on mma.sync =====================================
__global__ __launch_bounds__(256, 1) void qgemm_mma(
    const u16* __restrict__ Xt, const u16* __restrict__ Wq,
    u16* __restrict__ qbf) {
    extern __shared__ char sm[];
    const u32 sb = smem_u32(sm);
    const int tid = threadIdx.x;
    const int l = tid & 31, wid = tid >> 5;
    const int wm = wid & 3, wo = wid >> 2;
    const int blkn = blockIdx.x, blko = blockIdx.y, bb = blockIdx.z;

    const u16* XtB = Xt + (size_t)(bb * NDIM + blkn * 128) * 512;
    const u16* WqB = Wq + (size_t)(blko * 128) * 512;

    float acc[2][8][4];
    #pragma unroll
    for (int a = 0; a < 2; ++a)
        #pragma unroll
        for (int c = 0; c < 8; ++c)
            #pragma unroll
            for (int d = 0; d < 4; ++d) acc[a][c][d] = 0.f;

    u32 rowA[2], rowB[4];
    #pragma unroll
    for (int mt = 0; mt < 2; ++mt)
        rowA[mt] = (u32)(wm * 32 + mt * 16 + (l & 7) + (l & 8)) * 128;
    #pragma unroll
    for (int g = 0; g < 4; ++g)
        rowB[g] = (u32)(wo * 64 + g * 16 + (l & 7) + ((l & 16) >> 1)) * 128;

    for (int kc = 0; kc < 4; ++kc) {
        for (int i = tid; i < 1024; i += 256) {
            const int row = i >> 3, ch = i & 7;
            const u32 dst = sw128((u32)(row * 128 + ch * 16));
            const size_t off = (size_t)row * 512 + kc * 64 + ch * 8;
            *(uint4*)(sm + dst)         = *(const uint4*)(XtB + off);
            *(uint4*)(sm + 16384 + dst) = *(const uint4*)(XtB + off + 256);
            *(uint4*)(sm + 32768 + dst) = *(const uint4*)(WqB + off);
            *(uint4*)(sm + 49152 + dst) = *(const uint4*)(WqB + off + 256);
        }
        __syncthreads();
        #pragma unroll
        for (int s = 0; s < 4; ++s) {
            const u32 cA = ((u32)((2 * s + ((l >> 4) & 1)) ^ (l & 7))) << 4;
            const u32 cB = ((u32)((2 * s + ((l >> 3) & 1)) ^ (l & 7))) << 4;
            u32 ah[2][4], al[2][4], bhf[4][4], blf[4][4];
            #pragma unroll
            for (int mt = 0; mt < 2; ++mt) {
                ldm_x4(ah[mt], sb + rowA[mt] + cA);
                ldm_x4(al[mt], sb + 16384 + rowA[mt] + cA);
            }
            #pragma unroll
            for (int g = 0; g < 4; ++g) {
                ldm_x4(bhf[g], sb + 32768 + rowB[g] + cB);
                ldm_x4(blf[g], sb + 49152 + rowB[g] + cB);
            }
            #pragma unroll
            for (int mt = 0; mt < 2; ++mt)
                #pragma unroll
                for (int g = 0; g < 4; ++g)
                    #pragma unroll
                    for (int hf = 0; hf < 2; ++hf) {
                        float* A4 = acc[mt][g * 2 + hf];
                        mma_a(A4[0], A4[1], A4[2], A4[3],
                              ah[mt][0], ah[mt][1], ah[mt][2], ah[mt][3],
                              bhf[g][2 * hf], bhf[g][2 * hf + 1]);
                        mma_a(A4[0], A4[1], A4[2], A4[3],
                              ah[mt][0], ah[mt][1], ah[mt][2], ah[mt][3],
                              blf[g][2 * hf], blf[g][2 * hf + 1]);
                        mma_a(A4[0], A4[1], A4[2], A4[3],
                              al[mt][0], al[mt][1], al[mt][2], al[mt][3],
                              bhf[g][2 * hf], bhf[g][2 * hf + 1]);
                    }
        }
        __syncthreads();
    }

    #pragma unroll
    for (int mt = 0; mt < 2; ++mt) {
        const int n0g = blkn * 128 + wm * 32 + mt * 16 + (l >> 2);
        #pragma unroll
        for (int nt = 0; nt < 8; ++nt) {
            const int o = blko * 128 + wo * 64 + nt * 8 + 2 * (l & 3);
            const int bh_ = bb * NHEADS + (o >> 5);
            const int d = o & 31;
            u16* base = qbf + ((size_t)bh_ * NDIM + n0g) * 64 + d;
            u32 hi0, lo0; split2u32(acc[mt][nt][0], acc[mt][nt][1], hi0, lo0);
            *(u32*)base = hi0; *(u32*)(base + 32) = lo0;
            u32 hi1, lo1; split2u32(acc[mt][nt][2], acc[mt][nt][3], hi1, lo1);
            u16* base2 = base + 8 * 64;
            *(u32*)base2 = hi1; *(u32*)(base2 + 32) = lo1;
        }
    }
}

// ===================== conv GEMM on mma.sync (split-K=8) ======================
__global__ __launch_bounds__(256, 1) void convgemm_mma(
    const u16* __restrict__ Wsr, const u16* __restrict__ Xp,
    float* __restrict__ part) {
    extern __shared__ char sm[];
    const u32 sb = smem_u32(sm);
    const int tid = threadIdx.x;
    const int l = tid & 31, wid = tid >> 5;
    const int wm = wid & 3, wo = wid >> 2;
    const int blkm = blockIdx.x, blko = blockIdx.y;
    const int zz = blockIdx.z;
    const int bb = zz & 1, ks = zz >> 1;

    const u16* AB = Wsr + (size_t)(blko * 128) * 8192;
    const u16* BB = Xp + (size_t)(bb * NKV + blkm * 128) * 8192;

    float acc[2][8][4];
    #pragma unroll
    for (int a = 0; a < 2; ++a)
        #pragma unroll
        for (int c = 0; c < 8; ++c)
            #pragma unroll
            for (int d = 0; d < 4; ++d) acc[a][c][d] = 0.f;

    u32 rowA[2], rowB[4];
    #pragma unroll
    for (int mt = 0; mt < 2; ++mt)
        rowA[mt] = (u32)(wm * 32 + mt * 16 + (l & 7) + (l & 8)) * 128;
    #pragma unroll
    for (int g = 0; g < 4; ++g)
        rowB[g] = (u32)(wo * 64 + g * 16 + (l & 7) + ((l & 16) >> 1)) * 128;

    for (int kcl = 0; kcl < 8; ++kcl) {
        const int kcg = ks * 8 + kcl;
        for (int i = tid; i < 1024; i += 256) {
            const int row = i >> 3, ch = i & 7;
            const u32 dst = sw128((u32)(row * 128 + ch * 16));
            const size_t off = (size_t)row * 8192 + kcg * 64 + ch * 8;
            *(uint4*)(sm + dst)         = *(const uint4*)(AB + off);
            *(uint4*)(sm + 16384 + dst) = *(const uint4*)(AB + off + 4096);
            *(uint4*)(sm + 32768 + dst) = *(const uint4*)(BB + off);
            *(uint4*)(sm + 49152 + dst) = *(const uint4*)(BB + off + 4096);
        }
        __syncthreads();
        #pragma unroll
        for (int s = 0; s < 4; ++s) {
            const u32 cA = ((u32)((2 * s + ((l >> 4) & 1)) ^ (l & 7))) << 4;
            const u32 cB = ((u32)((2 * s + ((l >> 3) & 1)) ^ (l & 7))) << 4;
            u32 ah[2][4], al[2][4], bhf[4][4], blf[4][4];
            #pragma unroll
            for (int mt = 0; mt < 2; ++mt) {
                ldm_x4(ah[mt], sb + rowA[mt] + cA);
                ldm_x4(al[mt], sb + 16384 + rowA[mt] + cA);
            }
            #pragma unroll
            for (int g = 0; g < 4; ++g) {
                ldm_x4(bhf[g], sb + 32768 + rowB[g] + cB);
                ldm_x4(blf[g], sb + 49152 + rowB[g] + cB);
            }
            #pragma unroll
            for (int mt = 0; mt < 2; ++mt)
                #pragma unroll
                for (int g = 0; g < 4; ++g)
                    #pragma unroll
                    for (int hf = 0; hf < 2; ++hf) {
                        float* A4 = acc[mt][g * 2 + hf];
                        mma_a(A4[0], A4[1], A4[2], A4[3],
                              ah[mt][0], ah[mt][1], ah[mt][2], ah[mt][3],
                              bhf[g][2 * hf], bhf[g][2 * hf + 1]);
                        mma_a(A4[0], A4[1], A4[2], A4[3],
                              ah[mt][0], ah[mt][1], ah[mt][2], ah[mt][3],
                              blf[g][2 * hf], blf[g][2 * hf + 1]);
                        mma_a(A4[0], A4[1], A4[2], A4[3],
                              al[mt][0], al[mt][1], al[mt][2], al[mt][3],
                              bhf[g][2 * hf], bhf[g][2 * hf + 1]);
                    }
        }
        __syncthreads();
    }

    #pragma unroll
    for (int mt = 0; mt < 2; ++mt) {
        const int o = blko * 128 + wm * 32 + mt * 16 + (l >> 2);
        #pragma unroll
        for (int nt = 0; nt < 8; ++nt) {
            const int m = blkm * 128 + wo * 64 + nt * 8 + 2 * (l & 3);
            float* dst = part + ((size_t)zz * CDIM + o) * NKV + m;
            *(float2*)dst = make_float2(acc[mt][nt][0], acc[mt][nt][1]);
            *(float2*)(dst + 8 * NKV) = make_float2(acc[mt][nt][2], acc[mt][nt][3]);
        }
    }
}

// ===================== conv reduce + BN =======================================
__global__ __launch_bounds__(256) void conv_reduce_bn(
    const float* __restrict__ part,
    const float* __restrict__ gam, const float* __restrict__ bet,
    const float* __restrict__ mu,  const float* __restrict__ var,
    float* __restrict__ xr) {
    const int idx = blockIdx.x * 256 + threadIdx.x;
    const int fl = idx * 4;
    const int b = fl >> 18;
    const int o = (fl >> 10) & 255;
    const int m = fl & 1023;
    float4 s = make_float4(0.f, 0.f, 0.f, 0.f);
    #pragma unroll
    for (int ks = 0; ks < 8; ++ks) {
        const float4 p = *(const float4*)&part[((size_t)(ks * 2 + b) * CDIM + o) * NKV + m];
        s.x += p.x; s.y += p.y; s.z += p.z; s.w += p.w;
    }
    const float inv = gam[o] * rsqrtf(var[o] + EPSBN);
    const float mb = mu[o], be = bet[o];
    float4 r = make_float4((s.x - mb) * inv + be, (s.y - mb) * inv + be,
                           (s.z - mb) * inv + be, (s.w - mb) * inv + be);
    *(float4*)&xr[((size_t)(b * CDIM + o)) * NKV + m] = r;
}

// ===================== k GEMM (scalar f32x2, split-bf16 epilogue) =============
__global__ __launch_bounds__(256) void gemm_split(
    const float* __restrict__ W, const float* __restrict__ X,
    u16* __restrict__ Out, int Ncol) {
    __shared__ float As[16][64];
    __shared__ float Bs[16][64];
    const int b  = blockIdx.z;
    const float* Xb = X + (size_t)b * CDIM * Ncol;
    const int bm = blockIdx.y * 64;
    const int bn = blockIdx.x * 64;
    const int tid = threadIdx.x;
    const int tm = tid >> 4, tn = tid & 15;

    u64 acc[4][2] = {};
    for (int k0 = 0; k0 < CDIM; k0 += 16) {
        const int ar = tid >> 2, ac = (tid & 3) * 4;
        float4 a4 = *(const float4*)&W[(size_t)(bm + ar) * CDIM + k0 + ac];
        As[ac + 0][ar] = a4.x; As[ac + 1][ar] = a4.y;
        As[ac + 2][ar] = a4.z; As[ac + 3][ar] = a4.w;
        const int br = tid >> 4, bc = (tid & 15) * 4;
        *(float4*)&Bs[br][bc] = *(const float4*)&Xb[(size_t)(k0 + br) * Ncol + bn + bc];
        __syncthreads();
        #pragma unroll
        for (int kk = 0; kk < 16; ++kk) {
            float4 av = *(const float4*)&As[kk][tm * 4];
            ulonglong2 bv = *(const ulonglong2*)&Bs[kk][tn * 4];
            u64 a0 = pack2(av.x, av.x), a1 = pack2(av.y, av.y);
            u64 a2 = pack2(av.z, av.z), a3 = pack2(av.w, av.w);
            acc[0][0] = fma2(a0, bv.x, acc[0][0]); acc[0][1] = fma2(a0, bv.y, acc[0][1]);
            acc[1][0] = fma2(a1, bv.x, acc[1][0]); acc[1][1] = fma2(a1, bv.y, acc[1][1]);
            acc[2][0] = fma2(a2, bv.x, acc[2][0]); acc[2][1] = fma2(a2, bv.y, acc[2][1]);
            acc[3][0] = fma2(a3, bv.x, acc[3][0]); acc[3][1] = fma2(a3, bv.y, acc[3][1]);
        }
        __syncthreads();
    }
    const int o0 = bm + tm * 4;
    const int d0 = o0 & 31;
    const int bh = b * NHEADS + (o0 >> 5);
    #pragma unroll
    for (int j = 0; j < 4; ++j) {
        const int col = bn + tn * 4 + j;
        u64 hi_pack = 0, lo_pack = 0;
        #pragma unroll
        for (int i = 0; i < 4; ++i) {
            float2 f = unpack2(acc[i][j >> 1]);
            float v = (j & 1) ? f.y : f.x;
            u16 h, lw; split1(v, h, lw);
            hi_pack |= (u64)h << (16 * i);
            lo_pack |= (u64)lw << (16 * i);
        }
        u16* base = Out + ((size_t)bh * Ncol + col) * 64 + d0;
        *(u64*)base        = hi_pack;
        *(u64*)(base + 32) = lo_pack;
    }
}

// ---------------- v = mean_n x ------------------------------------------------
__global__ __launch_bounds__(256) void mean_v(const float* __restrict__ x,
                                              float* __restrict__ v) {
    const int bc = blockIdx.x;
    const float* xp = x + (size_t)bc * NDIM;
    float s = 0.f;
    for (int i = threadIdx.x * 4; i < NDIM; i += 256 * 4) {
        float4 t = *(const float4*)&xp[i];
        s += (t.x + t.y) + (t.z + t.w);
    }
    __shared__ float red[256];
    red[threadIdx.x] = s;
    __syncthreads();
    for (int st = 128; st > 0; st >>= 1) {
        if (threadIdx.x < st) red[threadIdx.x] += red[threadIdx.x + st];
        __syncthreads();
    }
    if (threadIdx.x == 0) v[bc] = red[0] * (1.0f / NDIM);
}

// ---------------- alpha/bias --------------------------------------------------
__global__ __launch_bounds__(256) void alpha_kernel(
    const float* __restrict__ wproj, const float* __restrict__ v,
    const float* __restrict__ gam, const float* __restrict__ bet,
    const float* __restrict__ mu,  const float* __restrict__ var,
    float* __restrict__ alpha, float* __restrict__ bias) {
    const int b = blockIdx.x;
    const int o = threadIdx.x;
    __shared__ float vs[CDIM];
    vs[o] = v[b * CDIM + o];
    __syncthreads();
    float p = 0.f;
    const float* wr = wproj + (size_t)o * CDIM;
    #pragma unroll 8
    for (int c = 0; c < CDIM; ++c) p = fmaf(wr[c], vs[c], p);
    const float inv = gam[o] * rsqrtf(var[o] + EPSBN);
    alpha[b * CDIM + o] = p * inv;
    if (b == 0) bias[o] = bet[o] - mu[o] * inv;
}

// ===================== mma.sync attention (256 threads, 2-chain ILP) ==========
#define SM_QOFF 131072
#define SM_TOT  147456
#define NTILES  16

__global__ __launch_bounds__(256, 1)
void attn_mma(const u16* __restrict__ qbf, const u16* __restrict__ kbf,
              float* __restrict__ attn) {
    extern __shared__ char smem[];
    const u32 sb  = smem_u32(smem);
    const u32 ksb = sb;
    const u32 qsb = sb + SM_QOFF;
    const int tid = threadIdx.x;
    const int wid = tid >> 5, l = tid & 31;
    const int bh  = blockIdx.x >> 3;
    const int seg = blockIdx.x & 7;

    // stage k (1024 rows x 128B) swizzled
    {
        const uint4* ksrc = (const uint4*)(kbf + (size_t)bh * NKV * 64);
        for (int idx = tid; idx < NKV * 8; idx += 256) {
            const int row = idx >> 3, c = idx & 7;
            *(uint4*)(smem + sw128(row * 128 + c * 16)) = ksrc[idx];
        }
    }
    __syncthreads();

    const int brow = (l & 7) + ((l & 16) >> 1);
    u32 baddr[4];
    #pragma unroll
    for (int s = 0; s < 4; ++s)
        baddr[s] = ksb + brow * 128 + ((u32)((2 * s + ((l >> 3) & 1)) ^ (l & 7)) << 4);

    const int arow = (l & 7) + (l & 8);
    u32 aaddr[4];
    #pragma unroll
    for (int s = 0; s < 4; ++s)
        aaddr[s] = qsb + arow * 128 + ((u32)((2 * s + ((l >> 4) & 1)) ^ (l & 7)) << 4);

    const float scale = 0.17677669529663687f;
    float* ob = attn + (size_t)bh * NDIM;

    for (int t = 0; t < NTILES; ++t) {
        const int n_base = (seg * NTILES + t) * 128;
        // q tile store: warp w writes its own rows 16w..16w+15 (row = tid>>1)
        {
            const uint4* qsrc = (const uint4*)(qbf + ((size_t)bh * NDIM + n_base) * 64);
            const int row = tid >> 1;
            const int j0 = (tid & 1) * 4;
            #pragma unroll
            for (int j = 0; j < 4; ++j)
                *(uint4*)(smem + SM_QOFF + sw128(row * 128 + (j0 + j) * 16))
                    = qsrc[(size_t)row * 8 + j0 + j];
        }
        __syncwarp();

        // A frags: this warp's 16 rows; s=0 qhi d0-15, 1 qhi d16-31, 2 qlo d0-15, 3 qlo d16-31
        u32 a[4][4];
        {
            const u32 roff = (u32)(wid * 16) * 128;
            #pragma unroll
            for (int s = 0; s < 4; ++s)
                ldm_x4(a[s], aaddr[s] + roff);
        }
        __syncwarp();

        float rmax[2] = {-INFINITY, -INFINITY};
        for (int kv = 0; kv < 64; ++kv) {
            const u32 off = (u32)kv * 2048;
            u32 bh0[4], bh1[4], bl0[4], bl1[4];
            ldm_x4(bh0, baddr[0] + off);
            ldm_x4(bh1, baddr[1] + off);
            ldm_x4(bl0, baddr[2] + off);
            ldm_x4(bl1, baddr[3] + off);
            #pragma unroll
            for (int g = 0; g < 2; ++g) {
                // chain A: d0-15 terms; chain B: d16-31 terms (independent)
                float A0, A1, A2, A3, B0, B1, B2, B3;
                mma_z(A0, A1, A2, A3, a[0][0], a[0][1], a[0][2], a[0][3],
                      bh0[2 * g], bh0[2 * g + 1]);
                mma_z(B0, B1, B2, B3, a[1][0], a[1][1], a[1][2], a[1][3],
                      bh1[2 * g], bh1[2 * g + 1]);
                mma_a(A0, A1, A2, A3, a[0][0], a[0][1], a[0][2], a[0][3],
                      bl0[2 * g], bl0[2 * g + 1]);
                mma_a(B0, B1, B2, B3, a[1][0], a[1][1], a[1][2], a[1][3],
                      bl1[2 * g], bl1[2 * g + 1]);
                mma_a(A0, A1, A2, A3, a[2][0], a[2][1], a[2][2], a[2][3],
                      bh0[2 * g], bh0[2 * g + 1]);
                mma_a(B0, B1, B2, B3, a[3][0], a[3][1], a[3][2], a[3][3],
                      bh1[2 * g], bh1[2 * g + 1]);
                rmax[0] = fmaxf(rmax[0], fmaxf(A0 + B0, A1 + B1));
                rmax[1] = fmaxf(rmax[1], fmaxf(A2 + B2, A3 + B3));
            }
        }
        #pragma unroll
        for (int rr = 0; rr < 2; ++rr) {
            float v = rmax[rr];
            v = fmaxf(v, __shfl_xor_sync(0xffffffffu, v, 1));
            v = fmaxf(v, __shfl_xor_sync(0xffffffffu, v, 2));
            rmax[rr] = v;
        }
        if ((l & 3) == 0) {
            const int rbase = n_base + wid * 16;
            ob[rbase + (l >> 2) + 0] = rmax[0] * scale;
            ob[rbase + (l >> 2) + 8] = rmax[1] * scale;
        }
        __syncwarp();
    }
}

// ---------------- S[b][n] = sum_h attn ----------------------------------------
__global__ __launch_bounds__(256) void reduce_attn(const float* __restrict__ attn,
                                                   float* __restrict__ S) {
    const int idx = blockIdx.x * 256 + threadIdx.x;
    const int b = idx >> 14, n = idx & (NDIM - 1);
    float s = 0.f;
    #pragma unroll
    for (int h = 0; h < NHEADS; ++h)
        s += attn[((size_t)b * NHEADS + h) * NDIM + n];
    S[idx] = s;
}

// ---------------- out = alpha*S + bias -----------------------------------------
__global__ __launch_bounds__(256) void final_kernel(
    const float* __restrict__ S, const float* __restrict__ alpha,
    const float* __restrict__ bias, float* __restrict__ out) {
    const size_t t = (size_t)blockIdx.x * 256 + threadIdx.x;
    const size_t idx4 = t * 4;
    const int bo = (int)(idx4 >> 14);
    const int n  = (int)(idx4 & (NDIM - 1));
    const int b  = bo >> 8, o = bo & 255;
    const float a  = alpha[bo];
    const float bi = bias[o];
    float4 s = *(const float4*)&S[(size_t)b * NDIM + n];
    float4 r;
    r.x = fmaf(a, s.x, bi); r.y = fmaf(a, s.y, bi);
    r.z = fmaf(a, s.z, bi); r.w = fmaf(a, s.w, bi);
    *(float4*)&out[idx4] = r;
}

// ===================== launch ==================================================
extern "C" void kernel_launch(void* const* d_in, const int* in_sizes, int n_in,
                              void* d_out, int out_size) {
    const float* x      = (const float*)d_in[0];
    const float* w_q    = (const float*)d_in[1];
    const float* w_k    = (const float*)d_in[2];
    const float* w_sr   = (const float*)d_in[3];
    const float* sr_g   = (const float*)d_in[4];
    const float* sr_b   = (const float*)d_in[5];
    const float* sr_m   = (const float*)d_in[6];
    const float* sr_v   = (const float*)d_in[7];
    const float* w_proj = (const float*)d_in[8];
    const float* pj_g   = (const float*)d_in[9];
    const float* pj_b   = (const float*)d_in[10];
    const float* pj_m   = (const float*)d_in[11];
    const float* pj_v   = (const float*)d_in[12];
    float* out = (float*)d_out;

    u16 *qbf, *kbf, *Xt, *Xp, *wqs, *wsrs;
    float *part, *xr, *attn, *S, *v, *alpha, *bias;
    cudaGetSymbolAddress((void**)&qbf,   g_qbf);
    cudaGetSymbolAddress((void**)&kbf,   g_kbf);
    cudaGetSymbolAddress((void**)&Xt,    g_Xt);
    cudaGetSymbolAddress((void**)&Xp,    g_Xp);
    cudaGetSymbolAddress((void**)&wqs,   g_wqs);
    cudaGetSymbolAddress((void**)&wsrs,  g_wsrs);
    cudaGetSymbolAddress((void**)&part,  g_part);
    cudaGetSymbolAddress((void**)&xr,    g_xr);
    cudaGetSymbolAddress((void**)&attn,  g_attn);
    cudaGetSymbolAddress((void**)&S,     g_S);
    cudaGetSymbolAddress((void**)&v,     g_v);
    cudaGetSymbolAddress((void**)&alpha, g_alpha);
    cudaGetSymbolAddress((void**)&bias,  g_bias);

    cudaFuncSetAttribute(attn_mma, cudaFuncAttributeMaxDynamicSharedMemorySize, SM_TOT);
    cudaFuncSetAttribute(qgemm_mma, cudaFuncAttributeMaxDynamicSharedMemorySize, 65536);
    cudaFuncSetAttribute(convgemm_mma, cudaFuncAttributeMaxDynamicSharedMemorySize, 65536);
    cudaFuncSetAttribute(gather_patches, cudaFuncAttributeMaxDynamicSharedMemorySize, 65536);

    // prep
    convert_w<<<64, 256>>>(w_q, wqs, 256);
    convert_w<<<1024, 256>>>(w_sr, wsrs, 4096);
    transpose_split_x<<<dim3(256, 4, 2), 256>>>(x, Xt);
    gather_patches<<<dim3(8, 32, 2), 256, 65536>>>(x, Xp);
    // q = w_q @ x  (tensor cores)
    qgemm_mma<<<dim3(128, 2, 2), 256, 65536>>>(Xt, wqs, qbf);
    // xr = BN(conv_sr(x))  (tensor cores, split-K)
    convgemm_mma<<<dim3(8, 2, 16), 256, 65536>>>(wsrs, Xp, part);
    conv_reduce_bn<<<512, 256>>>(part, sr_g, sr_b, sr_m, sr_v, xr);
    // k = w_k @ xr (scalar, small)
    gemm_split<<<dim3(NKV / 64, CDIM / 64, BSZ), 256>>>(w_k, xr, kbf, NKV);
    // v, alpha
    mean_v<<<BSZ * CDIM, 256>>>(x, v);
    alpha_kernel<<<BSZ, CDIM>>>(w_proj, v, pj_g, pj_b, pj_m, pj_v, alpha, bias);
    // attention rowmax (tensor cores)
    attn_mma<<<128, 256, SM_TOT>>>(qbf, kbf, attn);
    // tail
    reduce_attn<<<BSZ * NDIM / 256, 256>>>(attn, S);
    final_kernel<<<(BSZ * CDIM * NDIM / 4) / 256, 256>>>(S, alpha, bias, out);
}

// round 7
// speedup vs baseline: 2.6363x; 1.0316x over previous
#include <cuda_runtime.h>
#include <cuda_bf16.h>
#include <math.h>
#include <cstdint>

// Problem constants
#define BSZ    2
#define CDIM   256
#define NDIM   16384      // 128*128
#define HDIM   128
#define WDIM   128
#define NKV    1024       // 32*32
#define NHEADS 8
#define HD     32
#define EPSBN  1e-5f
#define KSR    4096       // CDIM*4*4

typedef unsigned long long u64;
typedef unsigned int u32;
typedef unsigned short u16;

// ===================== f32x2 helpers (scalar k GEMM) ==========================
__device__ __forceinline__ u64 pack2(float lo, float hi) {
    u64 r; asm("mov.b64 %0, {%1, %2};" : "=l"(r) : "f"(lo), "f"(hi)); return r;
}
__device__ __forceinline__ u64 fma2(u64 a, u64 b, u64 c) {
    u64 d; asm("fma.rn.f32x2 %0, %1, %2, %3;" : "=l"(d) : "l"(a), "l"(b), "l"(c)); return d;
}
__device__ __forceinline__ float2 unpack2(u64 a) {
    float lo, hi; asm("mov.b64 {%0, %1}, %2;" : "=f"(lo), "=f"(hi) : "l"(a));
    return make_float2(lo, hi);
}

// ===================== mma/ldmatrix helpers ===================================
__device__ __forceinline__ u32 smem_u32(const void* p) {
    u32 a; asm("{ .reg .u64 t; cvta.to.shared.u64 t, %1; cvt.u32.u64 %0, t; }"
               : "=r"(a) : "l"(p)); return a;
}
__device__ __forceinline__ void ldm_x4(u32 r[4], u32 addr) {
    asm volatile("ldmatrix.sync.aligned.m8n8.x4.shared.b16 {%0,%1,%2,%3}, [%4];"
                 : "=r"(r[0]), "=r"(r[1]), "=r"(r[2]), "=r"(r[3]) : "r"(addr));
}
__device__ __forceinline__ void mma_z(float& c0, float& c1, float& c2, float& c3,
                                      u32 a0, u32 a1, u32 a2, u32 a3,
                                      u32 b0, u32 b1) {
    asm volatile("mma.sync.aligned.m16n8k16.row.col.f32.bf16.bf16.f32 "
                 "{%0,%1,%2,%3}, {%4,%5,%6,%7}, {%8,%9}, {%10,%10,%10,%10};"
                 : "=f"(c0), "=f"(c1), "=f"(c2), "=f"(c3)
                 : "r"(a0), "r"(a1), "r"(a2), "r"(a3), "r"(b0), "r"(b1), "f"(0.0f));
}
__device__ __forceinline__ void mma_a(float& c0, float& c1, float& c2, float& c3,
                                      u32 a0, u32 a1, u32 a2, u32 a3,
                                      u32 b0, u32 b1) {
    asm volatile("mma.sync.aligned.m16n8k16.row.col.f32.bf16.bf16.f32 "
                 "{%0,%1,%2,%3}, {%4,%5,%6,%7}, {%8,%9}, {%0,%1,%2,%3};"
                 : "+f"(c0), "+f"(c1), "+f"(c2), "+f"(c3)
                 : "r"(a0), "r"(a1), "r"(a2), "r"(a3), "r"(b0), "r"(b1));
}
__device__ __forceinline__ u32 sw128(u32 b) { return b ^ ((b >> 3) & 0x70); }

// ===================== bf16 split helpers =====================================
__device__ __forceinline__ void split1(float v, u16& h, u16& l) {
    __nv_bfloat16 hb = __float2bfloat16_rn(v);
    float hf = __bfloat162float(hb);
    __nv_bfloat16 lb = __float2bfloat16_rn(v - hf);
    h = __bfloat16_as_ushort(hb); l = __bfloat16_as_ushort(lb);
}
__device__ __forceinline__ void split4(float4 v, u64& hi, u64& lo) {
    u16 h0,l0,h1,l1,h2,l2,h3,l3;
    split1(v.x,h0,l0); split1(v.y,h1,l1); split1(v.z,h2,l2); split1(v.w,h3,l3);
    hi = (u64)h0 | ((u64)h1<<16) | ((u64)h2<<32) | ((u64)h3<<48);
    lo = (u64)l0 | ((u64)l1<<16) | ((u64)l2<<32) | ((u64)l3<<48);
}
__device__ __forceinline__ void split2u32(float v0, float v1, u32& hi, u32& lo) {
    u16 h0,l0,h1,l1; split1(v0,h0,l0); split1(v1,h1,l1);
    hi = (u32)h0 | ((u32)h1<<16); lo = (u32)l0 | ((u32)l1<<16);
}

// ===================== scratch ================================================
__device__ __align__(16) u16  g_qbf [BSZ * NHEADS * NDIM * 64];
__device__ __align__(16) u16  g_kbf [BSZ * NHEADS * NKV  * 64];
__device__ __align__(16) u16  g_Xt  [BSZ * NDIM * 512];    // [b,n][hi 256|lo 256]
__device__ __align__(16) u16  g_Xp  [BSZ * NKV * 8192];    // [b,m][hi 4096|lo 4096]
__device__ __align__(16) u16  g_wqs [CDIM * 512];
__device__ __align__(16) u16  g_wsrs[CDIM * 8192];
__device__ float g_part[16 * CDIM * NKV];                  // split-K partials
__device__ float g_xr  [BSZ * CDIM * NKV];
__device__ float g_attn[2 * BSZ * NHEADS * NDIM];          // [half][bh][n]
__device__ float g_S   [BSZ * NDIM];
__device__ float g_vp  [BSZ * CDIM * 256];                 // mean partials per n-tile
__device__ float g_v   [BSZ * CDIM];
__device__ float g_alpha[BSZ * CDIM];
__device__ float g_bias [CDIM];

// ===================== prep: W fp32 -> split bf16 rows ========================
__global__ __launch_bounds__(256) void convert_w(
    const float* __restrict__ W, u16* __restrict__ out, int K) {
    const int idx = blockIdx.x * 256 + threadIdx.x;
    const int fl = idx * 4;
    const int row = fl / K;
    const int k = fl - row * K;
    float4 v = *(const float4*)&W[fl];
    u64 hi, lo; split4(v, hi, lo);
    u16* o = out + (size_t)row * 2 * K + k;
    *(u64*)o = hi;
    *(u64*)(o + K) = lo;
}

// ===================== prep: x -> Xt (tile transpose + split + v partials) ====
// tile 64c x 64n; grid (N/64, C/64, B); 256 threads.
__global__ __launch_bounds__(256) void transpose_split_x(
    const float* __restrict__ x, u16* __restrict__ Xt, float* __restrict__ vp) {
    __shared__ float s[64][65];
    const int n0 = blockIdx.x * 64;
    const int c0 = blockIdx.y * 64;
    const int b  = blockIdx.z;
    const int tid = threadIdx.x;
    #pragma unroll
    for (int i = 0; i < 4; ++i) {
        const int idx = i * 256 + tid;
        const int c_l = idx >> 4, nq = idx & 15;
        float4 v = *(const float4*)&x[((size_t)(b * CDIM + c0 + c_l)) * NDIM + n0 + nq * 4];
        s[c_l][nq * 4 + 0] = v.x; s[c_l][nq * 4 + 1] = v.y;
        s[c_l][nq * 4 + 2] = v.z; s[c_l][nq * 4 + 3] = v.w;
    }
    __syncthreads();
    const int n_l = tid >> 2, cq = tid & 3;
    u16* orow = Xt + ((size_t)(b * NDIM + n0 + n_l)) * 512 + c0;
    #pragma unroll
    for (int i = 0; i < 4; ++i) {
        const int c_loc = (cq + i * 4) * 4;
        float4 v = make_float4(s[c_loc][n_l], s[c_loc + 1][n_l],
                               s[c_loc + 2][n_l], s[c_loc + 3][n_l]);
        u64 hi, lo; split4(v, hi, lo);
        *(u64*)(orow + c_loc) = hi;
        *(u64*)(orow + 256 + c_loc) = lo;
    }
    // v partials: sum over the 64 n in this tile for each c (deterministic slot)
    if (tid < 64) {
        float acc = 0.f;
        #pragma unroll 16
        for (int n = 0; n < 64; ++n) acc += s[tid][n];
        vp[((size_t)(b * CDIM + c0 + tid)) * 256 + blockIdx.x] = acc;
    }
}

// ---------------- v = mean (reduce partials) ----------------------------------
__global__ __launch_bounds__(256) void vp_reduce(const float* __restrict__ vp,
                                                 float* __restrict__ v) {
    const int bc = blockIdx.x;
    __shared__ float red[256];
    red[threadIdx.x] = vp[(size_t)bc * 256 + threadIdx.x];
    __syncthreads();
    for (int st = 128; st > 0; st >>= 1) {
        if (threadIdx.x < st) red[threadIdx.x] += red[threadIdx.x + st];
        __syncthreads();
    }
    if (threadIdx.x == 0) v[bc] = red[0] * (1.0f / NDIM);
}

// ===================== prep: x -> Xp (smem-staged patch gather + split) =======
__global__ __launch_bounds__(256) void gather_patches(
    const float* __restrict__ x, u16* __restrict__ Xp) {
    extern __shared__ char gsm[];   // [0,32768) hi, [32768,65536) lo
    const int cch = blockIdx.x;
    const int hh  = blockIdx.y;
    const int b   = blockIdx.z;
    const int tid = threadIdx.x;
    #pragma unroll
    for (int i = 0; i < 16; ++i) {
        const int idx = i * 256 + tid;
        const int c_l = idx >> 7;
        const int rem = idx & 127;
        const int p = rem >> 5, w4 = rem & 31;
        float4 v = *(const float4*)&x[((size_t)(b * CDIM + cch * 32 + c_l)) * NDIM
                                      + (hh * 4 + p) * WDIM + w4 * 4];
        u64 hi, lo; split4(v, hi, lo);
        const u32 off = (u32)(c_l * 32 + p * 8);
        const u32 phys = (off ^ ((u32)(w4 & 15) << 3)) + (u32)w4 * 1024;
        *(u64*)(gsm + phys) = hi;
        *(u64*)(gsm + 32768 + phys) = lo;
    }
    __syncthreads();
    #pragma unroll
    for (int i = 0; i < 16; ++i) {
        const int idx = i * 256 + tid;
        const int ww = idx >> 7, j = idx & 127;
        const u32 phys = (((u32)j * 8) ^ ((u32)(ww & 15) << 3)) + (u32)ww * 1024;
        u16* dst = Xp + ((size_t)(b * NKV + hh * 32 + ww)) * 8192 + cch * 512 + j * 4;
        *(u64*)dst = *(const u64*)(gsm + phys);
        *(u64*)(dst + 4096) = *(const u64*)(gsm + 32768 + phys);
    }
}

// ===================== q GEMM on mma.sync =====================================
__global__ __launch_bounds__(256, 1) void qgemm_mma(
    const u16* __restrict__ Xt, const u16* __restrict__ Wq,
    u16* __restrict__ qbf) {
    extern __shared__ char sm[];
    const u32 sb = smem_u32(sm);
    const int tid = threadIdx.x;
    const int l = tid & 31, wid = tid >> 5;
    const int wm = wid & 3, wo = wid >> 2;
    const int blkn = blockIdx.x, blko = blockIdx.y, bb = blockIdx.z;

    const u16* XtB = Xt + (size_t)(bb * NDIM + blkn * 128) * 512;
    const u16* WqB = Wq + (size_t)(blko * 128) * 512;

    float acc[2][8][4];
    #pragma unroll
    for (int a = 0; a < 2; ++a)
        #pragma unroll
        for (int c = 0; c < 8; ++c)
            #pragma unroll
            for (int d = 0; d < 4; ++d) acc[a][c][d] = 0.f;

    u32 rowA[2], rowB[4];
    #pragma unroll
    for (int mt = 0; mt < 2; ++mt)
        rowA[mt] = (u32)(wm * 32 + mt * 16 + (l & 7) + (l & 8)) * 128;
    #pragma unroll
    for (int g = 0; g < 4; ++g)
        rowB[g] = (u32)(wo * 64 + g * 16 + (l & 7) + ((l & 16) >> 1)) * 128;

    for (int kc = 0; kc < 4; ++kc) {
        for (int i = tid; i < 1024; i += 256) {
            const int row = i >> 3, ch = i & 7;
            const u32 dst = sw128((u32)(row * 128 + ch * 16));
            const size_t off = (size_t)row * 512 + kc * 64 + ch * 8;
            *(uint4*)(sm + dst)         = *(const uint4*)(XtB + off);
            *(uint4*)(sm + 16384 + dst) = *(const uint4*)(XtB + off + 256);
            *(uint4*)(sm + 32768 + dst) = *(const uint4*)(WqB + off);
            *(uint4*)(sm + 49152 + dst) = *(const uint4*)(WqB + off + 256);
        }
        __syncthreads();
        #pragma unroll
        for (int s = 0; s < 4; ++s) {
            const u32 cA = ((u32)((2 * s + ((l >> 4) & 1)) ^ (l & 7))) << 4;
            const u32 cB = ((u32)((2 * s + ((l >> 3) & 1)) ^ (l & 7))) << 4;
            u32 ah[2][4], al[2][4], bhf[4][4], blf[4][4];
            #pragma unroll
            for (int mt = 0; mt < 2; ++mt) {
                ldm_x4(ah[mt], sb + rowA[mt] + cA);
                ldm_x4(al[mt], sb + 16384 + rowA[mt] + cA);
            }
            #pragma unroll
            for (int g = 0; g < 4; ++g) {
                ldm_x4(bhf[g], sb + 32768 + rowB[g] + cB);
                ldm_x4(blf[g], sb + 49152 + rowB[g] + cB);
            }
            #pragma unroll
            for (int mt = 0; mt < 2; ++mt)
                #pragma unroll
                for (int g = 0; g < 4; ++g)
                    #pragma unroll
                    for (int hf = 0; hf < 2; ++hf) {
                        float* A4 = acc[mt][g * 2 + hf];
                        mma_a(A4[0], A4[1], A4[2], A4[3],
                              ah[mt][0], ah[mt][1], ah[mt][2], ah[mt][3],
                              bhf[g][2 * hf], bhf[g][2 * hf + 1]);
                        mma_a(A4[0], A4[1], A4[2], A4[3],
                              ah[mt][0], ah[mt][1], ah[mt][2], ah[mt][3],
                              blf[g][2 * hf], blf[g][2 * hf + 1]);
                        mma_a(A4[0], A4[1], A4[2], A4[3],
                              al[mt][0], al[mt][1], al[mt][2], al[mt][3],
                              bhf[g][2 * hf], bhf[g][2 * hf + 1]);
                    }
        }
        __syncthreads();
    }

    #pragma unroll
    for (int mt = 0; mt < 2; ++mt) {
        const int n0g = blkn * 128 + wm * 32 + mt * 16 + (l >> 2);
        #pragma unroll
        for (int nt = 0; nt < 8; ++nt) {
            const int o = blko * 128 + wo * 64 + nt * 8 + 2 * (l & 3);
            const int bh_ = bb * NHEADS + (o >> 5);
            const int d = o & 31;
            u16* base = qbf + ((size_t)bh_ * NDIM + n0g) * 64 + d;
            u32 hi0, lo0; split2u32(acc[mt][nt][0], acc[mt][nt][1], hi0, lo0);
            *(u32*)base = hi0; *(u32*)(base + 32) = lo0;
            u32 hi1, lo1; split2u32(acc[mt][nt][2], acc[mt][nt][3], hi1, lo1);
            u16* base2 = base + 8 * 64;
            *(u32*)base2 = hi1; *(u32*)(base2 + 32) = lo1;
        }
    }
}

// ===================== conv GEMM on mma.sync (split-K=8) ======================
__global__ __launch_bounds__(256, 1) void convgemm_mma(
    const u16* __restrict__ Wsr, const u16* __restrict__ Xp,
    float* __restrict__ part) {
    extern __shared__ char sm[];
    const u32 sb = smem_u32(sm);
    const int tid = threadIdx.x;
    const int l = tid & 31, wid = tid >> 5;
    const int wm = wid & 3, wo = wid >> 2;
    const int blkm = blockIdx.x, blko = blockIdx.y;
    const int zz = blockIdx.z;
    const int bb = zz & 1, ks = zz >> 1;

    const u16* AB = Wsr + (size_t)(blko * 128) * 8192;
    const u16* BB = Xp + (size_t)(bb * NKV + blkm * 128) * 8192;

    float acc[2][8][4];
    #pragma unroll
    for (int a = 0; a < 2; ++a)
        #pragma unroll
        for (int c = 0; c < 8; ++c)
            #pragma unroll
            for (int d = 0; d < 4; ++d) acc[a][c][d] = 0.f;

    u32 rowA[2], rowB[4];
    #pragma unroll
    for (int mt = 0; mt < 2; ++mt)
        rowA[mt] = (u32)(wm * 32 + mt * 16 + (l & 7) + (l & 8)) * 128;
    #pragma unroll
    for (int g = 0; g < 4; ++g)
        rowB[g] = (u32)(wo * 64 + g * 16 + (l & 7) + ((l & 16) >> 1)) * 128;

    for (int kcl = 0; kcl < 8; ++kcl) {
        const int kcg = ks * 8 + kcl;
        for (int i = tid; i < 1024; i += 256) {
            const int row = i >> 3, ch = i & 7;
            const u32 dst = sw128((u32)(row * 128 + ch * 16));
            const size_t off = (size_t)row * 8192 + kcg * 64 + ch * 8;
            *(uint4*)(sm + dst)         = *(const uint4*)(AB + off);
            *(uint4*)(sm + 16384 + dst) = *(const uint4*)(AB + off + 4096);
            *(uint4*)(sm + 32768 + dst) = *(const uint4*)(BB + off);
            *(uint4*)(sm + 49152 + dst) = *(const uint4*)(BB + off + 4096);
        }
        __syncthreads();
        #pragma unroll
        for (int s = 0; s < 4; ++s) {
            const u32 cA = ((u32)((2 * s + ((l >> 4) & 1)) ^ (l & 7))) << 4;
            const u32 cB = ((u32)((2 * s + ((l >> 3) & 1)) ^ (l & 7))) << 4;
            u32 ah[2][4], al[2][4], bhf[4][4], blf[4][4];
            #pragma unroll
            for (int mt = 0; mt < 2; ++mt) {
                ldm_x4(ah[mt], sb + rowA[mt] + cA);
                ldm_x4(al[mt], sb + 16384 + rowA[mt] + cA);
            }
            #pragma unroll
            for (int g = 0; g < 4; ++g) {
                ldm_x4(bhf[g], sb + 32768 + rowB[g] + cB);
                ldm_x4(blf[g], sb + 49152 + rowB[g] + cB);
            }
            #pragma unroll
            for (int mt = 0; mt < 2; ++mt)
                #pragma unroll
                for (int g = 0; g < 4; ++g)
                    #pragma unroll
                    for (int hf = 0; hf < 2; ++hf) {
                        float* A4 = acc[mt][g * 2 + hf];
                        mma_a(A4[0], A4[1], A4[2], A4[3],
                              ah[mt][0], ah[mt][1], ah[mt][2], ah[mt][3],
                              bhf[g][2 * hf], bhf[g][2 * hf + 1]);
                        mma_a(A4[0], A4[1], A4[2], A4[3],
                              ah[mt][0], ah[mt][1], ah[mt][2], ah[mt][3],
                              blf[g][2 * hf], blf[g][2 * hf + 1]);
                        mma_a(A4[0], A4[1], A4[2], A4[3],
                              al[mt][0], al[mt][1], al[mt][2], al[mt][3],
                              bhf[g][2 * hf], bhf[g][2 * hf + 1]);
                    }
        }
        __syncthreads();
    }

    #pragma unroll
    for (int mt = 0; mt < 2; ++mt) {
        const int o = blko * 128 + wm * 32 + mt * 16 + (l >> 2);
        #pragma unroll
        for (int nt = 0; nt < 8; ++nt) {
            const int m = blkm * 128 + wo * 64 + nt * 8 + 2 * (l & 3);
            float* dst = part + ((size_t)zz * CDIM + o) * NKV + m;
            *(float2*)dst = make_float2(acc[mt][nt][0], acc[mt][nt][1]);
            *(float2*)(dst + 8 * NKV) = make_float2(acc[mt][nt][2], acc[mt][nt][3]);
        }
    }
}

// ===================== conv reduce + BN =======================================
__global__ __launch_bounds__(256) void conv_reduce_bn(
    const float* __restrict__ part,
    const float* __restrict__ gam, const float* __restrict__ bet,
    const float* __restrict__ mu,  const float* __restrict__ var,
    float* __restrict__ xr) {
    const int idx = blockIdx.x * 256 + threadIdx.x;
    const int fl = idx * 4;
    const int b = fl >> 18;
    const int o = (fl >> 10) & 255;
    const int m = fl & 1023;
    float4 s = make_float4(0.f, 0.f, 0.f, 0.f);
    #pragma unroll
    for (int ks = 0; ks < 8; ++ks) {
        const float4 p = *(const float4*)&part[((size_t)(ks * 2 + b) * CDIM + o) * NKV + m];
        s.x += p.x; s.y += p.y; s.z += p.z; s.w += p.w;
    }
    const float inv = gam[o] * rsqrtf(var[o] + EPSBN);
    const float mb = mu[o], be = bet[o];
    float4 r = make_float4((s.x - mb) * inv + be, (s.y - mb) * inv + be,
                           (s.z - mb) * inv + be, (s.w - mb) * inv + be);
    *(float4*)&xr[((size_t)(b * CDIM + o)) * NKV + m] = r;
}

// ===================== k GEMM (scalar f32x2, split-bf16 epilogue) =============
__global__ __launch_bounds__(256) void gemm_split(
    const float* __restrict__ W, const float* __restrict__ X,
    u16* __restrict__ Out, int Ncol) {
    __shared__ float As[16][64];
    __shared__ float Bs[16][64];
    const int b  = blockIdx.z;
    const float* Xb = X + (size_t)b * CDIM * Ncol;
    const int bm = blockIdx.y * 64;
    const int bn = blockIdx.x * 64;
    const int tid = threadIdx.x;
    const int tm = tid >> 4, tn = tid & 15;

    u64 acc[4][2] = {};
    for (int k0 = 0; k0 < CDIM; k0 += 16) {
        const int ar = tid >> 2, ac = (tid & 3) * 4;
        float4 a4 = *(const float4*)&W[(size_t)(bm + ar) * CDIM + k0 + ac];
        As[ac + 0][ar] = a4.x; As[ac + 1][ar] = a4.y;
        As[ac + 2][ar] = a4.z; As[ac + 3][ar] = a4.w;
        const int br = tid >> 4, bc = (tid & 15) * 4;
        *(float4*)&Bs[br][bc] = *(const float4*)&Xb[(size_t)(k0 + br) * Ncol + bn + bc];
        __syncthreads();
        #pragma unroll
        for (int kk = 0; kk < 16; ++kk) {
            float4 av = *(const float4*)&As[kk][tm * 4];
            ulonglong2 bv = *(const ulonglong2*)&Bs[kk][tn * 4];
            u64 a0 = pack2(av.x, av.x), a1 = pack2(av.y, av.y);
            u64 a2 = pack2(av.z, av.z), a3 = pack2(av.w, av.w);
            acc[0][0] = fma2(a0, bv.x, acc[0][0]); acc[0][1] = fma2(a0, bv.y, acc[0][1]);
            acc[1][0] = fma2(a1, bv.x, acc[1][0]); acc[1][1] = fma2(a1, bv.y, acc[1][1]);
            acc[2][0] = fma2(a2, bv.x, acc[2][0]); acc[2][1] = fma2(a2, bv.y, acc[2][1]);
            acc[3][0] = fma2(a3, bv.x, acc[3][0]); acc[3][1] = fma2(a3, bv.y, acc[3][1]);
        }
        __syncthreads();
    }
    const int o0 = bm + tm * 4;
    const int d0 = o0 & 31;
    const int bh = b * NHEADS + (o0 >> 5);
    #pragma unroll
    for (int j = 0; j < 4; ++j) {
        const int col = bn + tn * 4 + j;
        u64 hi_pack = 0, lo_pack = 0;
        #pragma unroll
        for (int i = 0; i < 4; ++i) {
            float2 f = unpack2(acc[i][j >> 1]);
            float v = (j & 1) ? f.y : f.x;
            u16 h, lw; split1(v, h, lw);
            hi_pack |= (u64)h << (16 * i);
            lo_pack |= (u64)lw << (16 * i);
        }
        u16* base = Out + ((size_t)bh * Ncol + col) * 64 + d0;
        *(u64*)base        = hi_pack;
        *(u64*)(base + 32) = lo_pack;
    }
}

// ---------------- alpha/bias --------------------------------------------------
__global__ __launch_bounds__(256) void alpha_kernel(
    const float* __restrict__ wproj, const float* __restrict__ v,
    const float* __restrict__ gam, const float* __restrict__ bet,
    const float* __restrict__ mu,  const float* __restrict__ var,
    float* __restrict__ alpha, float* __restrict__ bias) {
    const int b = blockIdx.x;
    const int o = threadIdx.x;
    __shared__ float vs[CDIM];
    vs[o] = v[b * CDIM + o];
    __syncthreads();
    float p = 0.f;
    const float* wr = wproj + (size_t)o * CDIM;
    #pragma unroll 8
    for (int c = 0; c < CDIM; ++c) p = fmaf(wr[c], vs[c], p);
    const float inv = gam[o] * rsqrtf(var[o] + EPSBN);
    alpha[b * CDIM + o] = p * inv;
    if (b == 0) bias[o] = bet[o] - mu[o] * inv;
}

// ===================== mma.sync attention (kv-split, 2 blocks/SM) =============
// grid (seg 8, half 2, bh 16); 256 threads; smem = k 64KB + q 16KB.
#define SM_QOFF 65536
#define SM_TOT  81920
#define NTILES  16

__global__ __launch_bounds__(256, 2)
void attn_mma(const u16* __restrict__ qbf, const u16* __restrict__ kbf,
              float* __restrict__ attn) {
    extern __shared__ char smem[];
    const u32 sb  = smem_u32(smem);
    const u32 ksb = sb;
    const u32 qsb = sb + SM_QOFF;
    const int tid = threadIdx.x;
    const int wid = tid >> 5, l = tid & 31;
    const int seg  = blockIdx.x;
    const int half = blockIdx.y;
    const int bh   = blockIdx.z;

    // stage this half's k (512 rows x 128B) swizzled
    {
        const uint4* ksrc = (const uint4*)(kbf + (size_t)(bh * NKV + half * 512) * 64);
        for (int idx = tid; idx < 512 * 8; idx += 256) {
            const int row = idx >> 3, c = idx & 7;
            *(uint4*)(smem + sw128(row * 128 + c * 16)) = ksrc[idx];
        }
    }
    __syncthreads();

    const int brow = (l & 7) + ((l & 16) >> 1);
    u32 baddr[4];
    #pragma unroll
    for (int s = 0; s < 4; ++s)
        baddr[s] = ksb + brow * 128 + ((u32)((2 * s + ((l >> 3) & 1)) ^ (l & 7)) << 4);

    const int arow = (l & 7) + (l & 8);
    u32 aaddr[4];
    #pragma unroll
    for (int s = 0; s < 4; ++s)
        aaddr[s] = qsb + arow * 128 + ((u32)((2 * s + ((l >> 4) & 1)) ^ (l & 7)) << 4);

    const float scale = 0.17677669529663687f;
    float* ob = attn + ((size_t)(half * 16 + bh)) * NDIM;

    for (int t = 0; t < NTILES; ++t) {
        const int n_base = (seg * NTILES + t) * 128;
        // q tile store: warp w writes rows 16w..16w+15 (row = tid>>1)
        {
            const uint4* qsrc = (const uint4*)(qbf + ((size_t)bh * NDIM + n_base) * 64);
            const int row = tid >> 1;
            const int j0 = (tid & 1) * 4;
            #pragma unroll
            for (int j = 0; j < 4; ++j)
                *(uint4*)(smem + SM_QOFF + sw128(row * 128 + (j0 + j) * 16))
                    = qsrc[(size_t)row * 8 + j0 + j];
        }
        __syncwarp();

        u32 a[4][4];
        {
            const u32 roff = (u32)(wid * 16) * 128;
            #pragma unroll
            for (int s = 0; s < 4; ++s)
                ldm_x4(a[s], aaddr[s] + roff);
        }
        __syncwarp();

        float rmax[2] = {-INFINITY, -INFINITY};
        for (int kv = 0; kv < 32; ++kv) {
            const u32 off = (u32)kv * 2048;
            u32 bh0[4], bh1[4], bl0[4], bl1[4];
            ldm_x4(bh0, baddr[0] + off);
            ldm_x4(bh1, baddr[1] + off);
            ldm_x4(bl0, baddr[2] + off);
            ldm_x4(bl1, baddr[3] + off);
            #pragma unroll
            for (int g = 0; g < 2; ++g) {
                float A0, A1, A2, A3, B0, B1, B2, B3;
                mma_z(A0, A1, A2, A3, a[0][0], a[0][1], a[0][2], a[0][3],
                      bh0[2 * g], bh0[2 * g + 1]);
                mma_z(B0, B1, B2, B3, a[1][0], a[1][1], a[1][2], a[1][3],
                      bh1[2 * g], bh1[2 * g + 1]);
                mma_a(A0, A1, A2, A3, a[0][0], a[0][1], a[0][2], a[0][3],
                      bl0[2 * g], bl0[2 * g + 1]);
                mma_a(B0, B1, B2, B3, a[1][0], a[1][1], a[1][2], a[1][3],
                      bl1[2 * g], bl1[2 * g + 1]);
                mma_a(A0, A1, A2, A3, a[2][0], a[2][1], a[2][2], a[2][3],
                      bh0[2 * g], bh0[2 * g + 1]);
                mma_a(B0, B1, B2, B3, a[3][0], a[3][1], a[3][2], a[3][3],
                      bh1[2 * g], bh1[2 * g + 1]);
                rmax[0] = fmaxf(rmax[0], fmaxf(A0 + B0, A1 + B1));
                rmax[1] = fmaxf(rmax[1], fmaxf(A2 + B2, A3 + B3));
            }
        }
        #pragma unroll
        for (int rr = 0; rr < 2; ++rr) {
            float v = rmax[rr];
            v = fmaxf(v, __shfl_xor_sync(0xffffffffu, v, 1));
            v = fmaxf(v, __shfl_xor_sync(0xffffffffu, v, 2));
            rmax[rr] = v;
        }
        if ((l & 3) == 0) {
            const int rbase = n_base + wid * 16;
            ob[rbase + (l >> 2) + 0] = rmax[0] * scale;
            ob[rbase + (l >> 2) + 8] = rmax[1] * scale;
        }
        __syncwarp();
    }
}

// ---------------- S[b][n] = sum_h max(half0, half1) ---------------------------
__global__ __launch_bounds__(256) void reduce_attn(const float* __restrict__ attn,
                                                   float* __restrict__ S) {
    const int idx = blockIdx.x * 256 + threadIdx.x;
    const int b = idx >> 14, n = idx & (NDIM - 1);
    float s = 0.f;
    #pragma unroll
    for (int h = 0; h < NHEADS; ++h) {
        const size_t base = ((size_t)(b * NHEADS + h)) * NDIM + n;
        s += fmaxf(attn[base], attn[base + (size_t)16 * NDIM]);
    }
    S[idx] = s;
}

// ---------------- out = alpha*S + bias -----------------------------------------
__global__ __launch_bounds__(256) void final_kernel(
    const float* __restrict__ S, const float* __restrict__ alpha,
    const float* __restrict__ bias, float* __restrict__ out) {
    const size_t t = (size_t)blockIdx.x * 256 + threadIdx.x;
    const size_t idx4 = t * 4;
    const int bo = (int)(idx4 >> 14);
    const int n  = (int)(idx4 & (NDIM - 1));
    const int b  = bo >> 8, o = bo & 255;
    const float a  = alpha[bo];
    const float bi = bias[o];
    float4 s = *(const float4*)&S[(size_t)b * NDIM + n];
    float4 r;
    r.x = fmaf(a, s.x, bi); r.y = fmaf(a, s.y, bi);
    r.z = fmaf(a, s.z, bi); r.w = fmaf(a, s.w, bi);
    *(float4*)&out[idx4] = r;
}

// ===================== launch ==================================================
extern "C" void kernel_launch(void* const* d_in, const int* in_sizes, int n_in,
                              void* d_out, int out_size) {
    const float* x      = (const float*)d_in[0];
    const float* w_q    = (const float*)d_in[1];
    const float* w_k    = (const float*)d_in[2];
    const float* w_sr   = (const float*)d_in[3];
    const float* sr_g   = (const float*)d_in[4];
    const float* sr_b   = (const float*)d_in[5];
    const float* sr_m   = (const float*)d_in[6];
    const float* sr_v   = (const float*)d_in[7];
    const float* w_proj = (const float*)d_in[8];
    const float* pj_g   = (const float*)d_in[9];
    const float* pj_b   = (const float*)d_in[10];
    const float* pj_m   = (const float*)d_in[11];
    const float* pj_v   = (const float*)d_in[12];
    float* out = (float*)d_out;

    u16 *qbf, *kbf, *Xt, *Xp, *wqs, *wsrs;
    float *part, *xr, *attn, *S, *vp, *v, *alpha, *bias;
    cudaGetSymbolAddress((void**)&qbf,   g_qbf);
    cudaGetSymbolAddress((void**)&kbf,   g_kbf);
    cudaGetSymbolAddress((void**)&Xt,    g_Xt);
    cudaGetSymbolAddress((void**)&Xp,    g_Xp);
    cudaGetSymbolAddress((void**)&wqs,   g_wqs);
    cudaGetSymbolAddress((void**)&wsrs,  g_wsrs);
    cudaGetSymbolAddress((void**)&part,  g_part);
    cudaGetSymbolAddress((void**)&xr,    g_xr);
    cudaGetSymbolAddress((void**)&attn,  g_attn);
    cudaGetSymbolAddress((void**)&S,     g_S);
    cudaGetSymbolAddress((void**)&vp,    g_vp);
    cudaGetSymbolAddress((void**)&v,     g_v);
    cudaGetSymbolAddress((void**)&alpha, g_alpha);
    cudaGetSymbolAddress((void**)&bias,  g_bias);

    cudaFuncSetAttribute(attn_mma, cudaFuncAttributeMaxDynamicSharedMemorySize, SM_TOT);
    cudaFuncSetAttribute(qgemm_mma, cudaFuncAttributeMaxDynamicSharedMemorySize, 65536);
    cudaFuncSetAttribute(convgemm_mma, cudaFuncAttributeMaxDynamicSharedMemorySize, 65536);
    cudaFuncSetAttribute(gather_patches, cudaFuncAttributeMaxDynamicSharedMemorySize, 65536);

    // prep
    convert_w<<<64, 256>>>(w_q, wqs, 256);
    convert_w<<<1024, 256>>>(w_sr, wsrs, 4096);
    transpose_split_x<<<dim3(256, 4, 2), 256>>>(x, Xt, vp);
    gather_patches<<<dim3(8, 32, 2), 256, 65536>>>(x, Xp);
    // q = w_q @ x  (tensor cores)
    qgemm_mma<<<dim3(128, 2, 2), 256, 65536>>>(Xt, wqs, qbf);
    // xr = BN(conv_sr(x))  (tensor cores, split-K)
    convgemm_mma<<<dim3(8, 2, 16), 256, 65536>>>(wsrs, Xp, part);
    conv_reduce_bn<<<512, 256>>>(part, sr_g, sr_b, sr_m, sr_v, xr);
    // k = w_k @ xr (scalar, small)
    gemm_split<<<dim3(NKV / 64, CDIM / 64, BSZ), 256>>>(w_k, xr, kbf, NKV);
    // v, alpha
    vp_reduce<<<BSZ * CDIM, 256>>>(vp, v);
    alpha_kernel<<<BSZ, CDIM>>>(w_proj, v, pj_g, pj_b, pj_m, pj_v, alpha, bias);
    // attention rowmax (tensor cores, kv-split for occupancy)
    attn_mma<<<dim3(8, 2, 16), 256, SM_TOT>>>(qbf, kbf, attn);
    // tail
    reduce_attn<<<BSZ * NDIM / 256, 256>>>(attn, S);
    final_kernel<<<(BSZ * CDIM * NDIM / 4) / 256, 256>>>(S, alpha, bias, out);
}

// round 8
// speedup vs baseline: 3.9289x; 1.4903x over previous
#include <cuda_runtime.h>
#include <cuda_fp16.h>
#include <math.h>
#include <cstdint>

// Problem constants
#define BSZ    2
#define CDIM   256
#define NDIM   16384      // 128*128
#define HDIM   128
#define WDIM   128
#define NKV    1024       // 32*32
#define NHEADS 8
#define HD     32
#define EPSBN  1e-5f
#define KSR    4096       // CDIM*4*4

typedef unsigned long long u64;
typedef unsigned int u32;
typedef unsigned short u16;

// ===================== f32x2 helpers (scalar k GEMM) ==========================
__device__ __forceinline__ u64 pack2(float lo, float hi) {
    u64 r; asm("mov.b64 %0, {%1, %2};" : "=l"(r) : "f"(lo), "f"(hi)); return r;
}
__device__ __forceinline__ u64 fma2(u64 a, u64 b, u64 c) {
    u64 d; asm("fma.rn.f32x2 %0, %1, %2, %3;" : "=l"(d) : "l"(a), "l"(b), "l"(c)); return d;
}
__device__ __forceinline__ float2 unpack2(u64 a) {
    float lo, hi; asm("mov.b64 {%0, %1}, %2;" : "=f"(lo), "=f"(hi) : "l"(a));
    return make_float2(lo, hi);
}

// ===================== mma/ldmatrix helpers (fp16) ============================
__device__ __forceinline__ u32 smem_u32(const void* p) {
    u32 a; asm("{ .reg .u64 t; cvta.to.shared.u64 t, %1; cvt.u32.u64 %0, t; }"
               : "=r"(a) : "l"(p)); return a;
}
__device__ __forceinline__ void ldm_x4(u32 r[4], u32 addr) {
    asm volatile("ldmatrix.sync.aligned.m8n8.x4.shared.b16 {%0,%1,%2,%3}, [%4];"
                 : "=r"(r[0]), "=r"(r[1]), "=r"(r[2]), "=r"(r[3]) : "r"(addr));
}
__device__ __forceinline__ void mma_z(float& c0, float& c1, float& c2, float& c3,
                                      u32 a0, u32 a1, u32 a2, u32 a3,
                                      u32 b0, u32 b1) {
    asm volatile("mma.sync.aligned.m16n8k16.row.col.f32.f16.f16.f32 "
                 "{%0,%1,%2,%3}, {%4,%5,%6,%7}, {%8,%9}, {%10,%10,%10,%10};"
                 : "=f"(c0), "=f"(c1), "=f"(c2), "=f"(c3)
                 : "r"(a0), "r"(a1), "r"(a2), "r"(a3), "r"(b0), "r"(b1), "f"(0.0f));
}
__device__ __forceinline__ void mma_a(float& c0, float& c1, float& c2, float& c3,
                                      u32 a0, u32 a1, u32 a2, u32 a3,
                                      u32 b0, u32 b1) {
    asm volatile("mma.sync.aligned.m16n8k16.row.col.f32.f16.f16.f32 "
                 "{%0,%1,%2,%3}, {%4,%5,%6,%7}, {%8,%9}, {%0,%1,%2,%3};"
                 : "+f"(c0), "+f"(c1), "+f"(c2), "+f"(c3)
                 : "r"(a0), "r"(a1), "r"(a2), "r"(a3), "r"(b0), "r"(b1));
}
__device__ __forceinline__ u32 sw128(u32 b) { return b ^ ((b >> 3) & 0x70); }

// ===================== fp16 pack/split helpers ================================
__device__ __forceinline__ u32 cvt2h(float a, float b) {
    __half2 h = __floats2half2_rn(a, b);
    return *reinterpret_cast<u32*>(&h);
}
__device__ __forceinline__ u64 cvt4h(float4 v) {
    u32 lo = cvt2h(v.x, v.y), hi = cvt2h(v.z, v.w);
    return (u64)lo | ((u64)hi << 32);
}
__device__ __forceinline__ void split1h(float v, u16& h, u16& l) {
    __half hh = __float2half_rn(v);
    float hf = __half2float(hh);
    __half lh = __float2half_rn(v - hf);
    h = *reinterpret_cast<u16*>(&hh); l = *reinterpret_cast<u16*>(&lh);
}
__device__ __forceinline__ void split4h(float4 v, u64& hi, u64& lo) {
    u16 h0,l0,h1,l1,h2,l2,h3,l3;
    split1h(v.x,h0,l0); split1h(v.y,h1,l1); split1h(v.z,h2,l2); split1h(v.w,h3,l3);
    hi = (u64)h0 | ((u64)h1<<16) | ((u64)h2<<32) | ((u64)h3<<48);
    lo = (u64)l0 | ((u64)l1<<16) | ((u64)l2<<32) | ((u64)l3<<48);
}

// ===================== scratch ================================================
__device__ __align__(16) u16  g_qbf [BSZ * NHEADS * NDIM * 32];  // fp16, 64B rows
__device__ __align__(16) u16  g_kbf [BSZ * NHEADS * NKV  * 32];  // fp16, 64B rows
__device__ __align__(16) u16  g_Xt  [BSZ * NDIM * 256];          // fp16 single
__device__ __align__(16) u16  g_Xp  [BSZ * NKV * 4096];          // fp16 single
__device__ __align__(16) u16  g_wqs [CDIM * 512];                // hi 256 | lo 256
__device__ __align__(16) u16  g_wsrs[CDIM * 8192];               // hi 4096 | lo 4096
__device__ float g_part[16 * CDIM * NKV];
__device__ float g_xr  [BSZ * CDIM * NKV];
__device__ float g_attn[2 * BSZ * NHEADS * NDIM];                // [half][bh][n]
__device__ float g_S   [BSZ * NDIM];
__device__ float g_vp  [BSZ * CDIM * 256];
__device__ float g_v   [BSZ * CDIM];
__device__ float g_alpha[BSZ * CDIM];
__device__ float g_bias [CDIM];

// ===================== prep: W fp32 -> split fp16 rows ========================
__global__ __launch_bounds__(256) void convert_w(
    const float* __restrict__ W, u16* __restrict__ out, int K) {
    const int idx = blockIdx.x * 256 + threadIdx.x;
    const int fl = idx * 4;
    const int row = fl / K;
    const int k = fl - row * K;
    float4 v = *(const float4*)&W[fl];
    u64 hi, lo; split4h(v, hi, lo);
    u16* o = out + (size_t)row * 2 * K + k;
    *(u64*)o = hi;
    *(u64*)(o + K) = lo;
}

// ===================== prep: x -> Xt (tile transpose -> fp16) + v partials ====
__global__ __launch_bounds__(256) void transpose_split_x(
    const float* __restrict__ x, u16* __restrict__ Xt, float* __restrict__ vp) {
    __shared__ float s[64][65];
    const int n0 = blockIdx.x * 64;
    const int c0 = blockIdx.y * 64;
    const int b  = blockIdx.z;
    const int tid = threadIdx.x;
    #pragma unroll
    for (int i = 0; i < 4; ++i) {
        const int idx = i * 256 + tid;
        const int c_l = idx >> 4, nq = idx & 15;
        float4 v = *(const float4*)&x[((size_t)(b * CDIM + c0 + c_l)) * NDIM + n0 + nq * 4];
        s[c_l][nq * 4 + 0] = v.x; s[c_l][nq * 4 + 1] = v.y;
        s[c_l][nq * 4 + 2] = v.z; s[c_l][nq * 4 + 3] = v.w;
    }
    __syncthreads();
    const int n_l = tid >> 2, cq = tid & 3;
    u16* orow = Xt + ((size_t)(b * NDIM + n0 + n_l)) * 256 + c0;
    #pragma unroll
    for (int i = 0; i < 4; ++i) {
        const int c_loc = (cq + i * 4) * 4;
        float4 v = make_float4(s[c_loc][n_l], s[c_loc + 1][n_l],
                               s[c_loc + 2][n_l], s[c_loc + 3][n_l]);
        *(u64*)(orow + c_loc) = cvt4h(v);
    }
    if (tid < 64) {
        float acc = 0.f;
        #pragma unroll 16
        for (int n = 0; n < 64; ++n) acc += s[tid][n];
        vp[((size_t)(b * CDIM + c0 + tid)) * 256 + blockIdx.x] = acc;
    }
}

// ---------------- v = mean (reduce partials) ----------------------------------
__global__ __launch_bounds__(256) void vp_reduce(const float* __restrict__ vp,
                                                 float* __restrict__ v) {
    const int bc = blockIdx.x;
    __shared__ float red[256];
    red[threadIdx.x] = vp[(size_t)bc * 256 + threadIdx.x];
    __syncthreads();
    for (int st = 128; st > 0; st >>= 1) {
        if (threadIdx.x < st) red[threadIdx.x] += red[threadIdx.x + st];
        __syncthreads();
    }
    if (threadIdx.x == 0) v[bc] = red[0] * (1.0f / NDIM);
}

// ===================== prep: x -> Xp (patch gather -> fp16) ===================
__global__ __launch_bounds__(256) void gather_patches(
    const float* __restrict__ x, u16* __restrict__ Xp) {
    extern __shared__ char gsm[];   // 32KB
    const int cch = blockIdx.x;
    const int hh  = blockIdx.y;
    const int b   = blockIdx.z;
    const int tid = threadIdx.x;
    #pragma unroll
    for (int i = 0; i < 16; ++i) {
        const int idx = i * 256 + tid;
        const int c_l = idx >> 7;
        const int rem = idx & 127;
        const int p = rem >> 5, w4 = rem & 31;
        float4 v = *(const float4*)&x[((size_t)(b * CDIM + cch * 32 + c_l)) * NDIM
                                      + (hh * 4 + p) * WDIM + w4 * 4];
        const u32 off = (u32)(c_l * 32 + p * 8);
        const u32 phys = (off ^ ((u32)(w4 & 15) << 3)) + (u32)w4 * 1024;
        *(u64*)(gsm + phys) = cvt4h(v);
    }
    __syncthreads();
    #pragma unroll
    for (int i = 0; i < 16; ++i) {
        const int idx = i * 256 + tid;
        const int ww = idx >> 7, j = idx & 127;
        const u32 phys = (((u32)j * 8) ^ ((u32)(ww & 15) << 3)) + (u32)ww * 1024;
        u16* dst = Xp + ((size_t)(b * NKV + hh * 32 + ww)) * 4096 + cch * 512 + j * 4;
        *(u64*)dst = *(const u64*)(gsm + phys);
    }
}

// ===================== q GEMM on mma.sync (X single, W split) =================
__global__ __launch_bounds__(256, 1) void qgemm_mma(
    const u16* __restrict__ Xt, const u16* __restrict__ Wq,
    u16* __restrict__ qbf) {
    extern __shared__ char sm[];
    const u32 sb = smem_u32(sm);
    const int tid = threadIdx.x;
    const int l = tid & 31, wid = tid >> 5;
    const int wm = wid & 3, wo = wid >> 2;
    const int blkn = blockIdx.x, blko = blockIdx.y, bb = blockIdx.z;

    const u16* XtB = Xt + (size_t)(bb * NDIM + blkn * 128) * 256;
    const u16* WqB = Wq + (size_t)(blko * 128) * 512;

    float acc[2][8][4];
    #pragma unroll
    for (int a = 0; a < 2; ++a)
        #pragma unroll
        for (int c = 0; c < 8; ++c)
            #pragma unroll
            for (int d = 0; d < 4; ++d) acc[a][c][d] = 0.f;

    u32 rowA[2], rowB[4];
    #pragma unroll
    for (int mt = 0; mt < 2; ++mt)
        rowA[mt] = (u32)(wm * 32 + mt * 16 + (l & 7) + (l & 8)) * 128;
    #pragma unroll
    for (int g = 0; g < 4; ++g)
        rowB[g] = (u32)(wo * 64 + g * 16 + (l & 7) + ((l & 16) >> 1)) * 128;

    for (int kc = 0; kc < 4; ++kc) {
        for (int i = tid; i < 1024; i += 256) {
            const int row = i >> 3, ch = i & 7;
            const u32 dst = sw128((u32)(row * 128 + ch * 16));
            *(uint4*)(sm + dst)         = *(const uint4*)(XtB + (size_t)row * 256 + kc * 64 + ch * 8);
            const size_t woff = (size_t)row * 512 + kc * 64 + ch * 8;
            *(uint4*)(sm + 16384 + dst) = *(const uint4*)(WqB + woff);
            *(uint4*)(sm + 32768 + dst) = *(const uint4*)(WqB + woff + 256);
        }
        __syncthreads();
        #pragma unroll
        for (int s = 0; s < 4; ++s) {
            const u32 cA = ((u32)((2 * s + ((l >> 4) & 1)) ^ (l & 7))) << 4;
            const u32 cB = ((u32)((2 * s + ((l >> 3) & 1)) ^ (l & 7))) << 4;
            u32 a[2][4], bhf[4][4], blf[4][4];
            #pragma unroll
            for (int mt = 0; mt < 2; ++mt)
                ldm_x4(a[mt], sb + rowA[mt] + cA);
            #pragma unroll
            for (int g = 0; g < 4; ++g) {
                ldm_x4(bhf[g], sb + 16384 + rowB[g] + cB);
                ldm_x4(blf[g], sb + 32768 + rowB[g] + cB);
            }
            #pragma unroll
            for (int mt = 0; mt < 2; ++mt)
                #pragma unroll
                for (int g = 0; g < 4; ++g)
                    #pragma unroll
                    for (int hf = 0; hf < 2; ++hf) {
                        float* A4 = acc[mt][g * 2 + hf];
                        mma_a(A4[0], A4[1], A4[2], A4[3],
                              a[mt][0], a[mt][1], a[mt][2], a[mt][3],
                              bhf[g][2 * hf], bhf[g][2 * hf + 1]);
                        mma_a(A4[0], A4[1], A4[2], A4[3],
                              a[mt][0], a[mt][1], a[mt][2], a[mt][3],
                              blf[g][2 * hf], blf[g][2 * hf + 1]);
                    }
        }
        __syncthreads();
    }

    // epilogue: single fp16 q rows (32 fp16 = 64B)
    #pragma unroll
    for (int mt = 0; mt < 2; ++mt) {
        const int n0g = blkn * 128 + wm * 32 + mt * 16 + (l >> 2);
        #pragma unroll
        for (int nt = 0; nt < 8; ++nt) {
            const int o = blko * 128 + wo * 64 + nt * 8 + 2 * (l & 3);
            const int bh_ = bb * NHEADS + (o >> 5);
            const int d = o & 31;
            u16* base = qbf + ((size_t)bh_ * NDIM + n0g) * 32 + d;
            *(u32*)base = cvt2h(acc[mt][nt][0], acc[mt][nt][1]);
            *(u32*)(base + 8 * 32) = cvt2h(acc[mt][nt][2], acc[mt][nt][3]);
        }
    }
}

// ===================== conv GEMM on mma.sync (W split, X single, split-K=8) ===
__global__ __launch_bounds__(256, 1) void convgemm_mma(
    const u16* __restrict__ Wsr, const u16* __restrict__ Xp,
    float* __restrict__ part) {
    extern __shared__ char sm[];
    const u32 sb = smem_u32(sm);
    const int tid = threadIdx.x;
    const int l = tid & 31, wid = tid >> 5;
    const int wm = wid & 3, wo = wid >> 2;
    const int blkm = blockIdx.x, blko = blockIdx.y;
    const int zz = blockIdx.z;
    const int bb = zz & 1, ks = zz >> 1;

    const u16* AB = Wsr + (size_t)(blko * 128) * 8192;
    const u16* BB = Xp + (size_t)(bb * NKV + blkm * 128) * 4096;

    float acc[2][8][4];
    #pragma unroll
    for (int a = 0; a < 2; ++a)
        #pragma unroll
        for (int c = 0; c < 8; ++c)
            #pragma unroll
            for (int d = 0; d < 4; ++d) acc[a][c][d] = 0.f;

    u32 rowA[2], rowB[4];
    #pragma unroll
    for (int mt = 0; mt < 2; ++mt)
        rowA[mt] = (u32)(wm * 32 + mt * 16 + (l & 7) + (l & 8)) * 128;
    #pragma unroll
    for (int g = 0; g < 4; ++g)
        rowB[g] = (u32)(wo * 64 + g * 16 + (l & 7) + ((l & 16) >> 1)) * 128;

    for (int kcl = 0; kcl < 8; ++kcl) {
        const int kcg = ks * 8 + kcl;
        for (int i = tid; i < 1024; i += 256) {
            const int row = i >> 3, ch = i & 7;
            const u32 dst = sw128((u32)(row * 128 + ch * 16));
            const size_t aoff = (size_t)row * 8192 + kcg * 64 + ch * 8;
            *(uint4*)(sm + dst)         = *(const uint4*)(AB + aoff);
            *(uint4*)(sm + 16384 + dst) = *(const uint4*)(AB + aoff + 4096);
            *(uint4*)(sm + 32768 + dst) = *(const uint4*)(BB + (size_t)row * 4096 + kcg * 64 + ch * 8);
        }
        __syncthreads();
        #pragma unroll
        for (int s = 0; s < 4; ++s) {
            const u32 cA = ((u32)((2 * s + ((l >> 4) & 1)) ^ (l & 7))) << 4;
            const u32 cB = ((u32)((2 * s + ((l >> 3) & 1)) ^ (l & 7))) << 4;
            u32 ah[2][4], al[2][4], bf[4][4];
            #pragma unroll
            for (int mt = 0; mt < 2; ++mt) {
                ldm_x4(ah[mt], sb + rowA[mt] + cA);
                ldm_x4(al[mt], sb + 16384 + rowA[mt] + cA);
            }
            #pragma unroll
            for (int g = 0; g < 4; ++g)
                ldm_x4(bf[g], sb + 32768 + rowB[g] + cB);
            #pragma unroll
            for (int mt = 0; mt < 2; ++mt)
                #pragma unroll
                for (int g = 0; g < 4; ++g)
                    #pragma unroll
                    for (int hf = 0; hf < 2; ++hf) {
                        float* A4 = acc[mt][g * 2 + hf];
                        mma_a(A4[0], A4[1], A4[2], A4[3],
                              ah[mt][0], ah[mt][1], ah[mt][2], ah[mt][3],
                              bf[g][2 * hf], bf[g][2 * hf + 1]);
                        mma_a(A4[0], A4[1], A4[2], A4[3],
                              al[mt][0], al[mt][1], al[mt][2], al[mt][3],
                              bf[g][2 * hf], bf[g][2 * hf + 1]);
                    }
        }
        __syncthreads();
    }

    #pragma unroll
    for (int mt = 0; mt < 2; ++mt) {
        const int o = blko * 128 + wm * 32 + mt * 16 + (l >> 2);
        #pragma unroll
        for (int nt = 0; nt < 8; ++nt) {
            const int m = blkm * 128 + wo * 64 + nt * 8 + 2 * (l & 3);
            float* dst = part + ((size_t)zz * CDIM + o) * NKV + m;
            *(float2*)dst = make_float2(acc[mt][nt][0], acc[mt][nt][1]);
            *(float2*)(dst + 8 * NKV) = make_float2(acc[mt][nt][2], acc[mt][nt][3]);
        }
    }
}

// ===================== conv reduce + BN =======================================
__global__ __launch_bounds__(256) void conv_reduce_bn(
    const float* __restrict__ part,
    const float* __restrict__ gam, const float* __restrict__ bet,
    const float* __restrict__ mu,  const float* __restrict__ var,
    float* __restrict__ xr) {
    const int idx = blockIdx.x * 256 + threadIdx.x;
    const int fl = idx * 4;
    const int b = fl >> 18;
    const int o = (fl >> 10) & 255;
    const int m = fl & 1023;
    float4 s = make_float4(0.f, 0.f, 0.f, 0.f);
    #pragma unroll
    for (int ks = 0; ks < 8; ++ks) {
        const float4 p = *(const float4*)&part[((size_t)(ks * 2 + b) * CDIM + o) * NKV + m];
        s.x += p.x; s.y += p.y; s.z += p.z; s.w += p.w;
    }
    const float inv = gam[o] * rsqrtf(var[o] + EPSBN);
    const float mb = mu[o], be = bet[o];
    float4 r = make_float4((s.x - mb) * inv + be, (s.y - mb) * inv + be,
                           (s.z - mb) * inv + be, (s.w - mb) * inv + be);
    *(float4*)&xr[((size_t)(b * CDIM + o)) * NKV + m] = r;
}

// ===================== k GEMM (scalar f32x2, fp16 epilogue) ===================
__global__ __launch_bounds__(256) void gemm_split(
    const float* __restrict__ W, const float* __restrict__ X,
    u16* __restrict__ Out, int Ncol) {
    __shared__ float As[16][64];
    __shared__ float Bs[16][64];
    const int b  = blockIdx.z;
    const float* Xb = X + (size_t)b * CDIM * Ncol;
    const int bm = blockIdx.y * 64;
    const int bn = blockIdx.x * 64;
    const int tid = threadIdx.x;
    const int tm = tid >> 4, tn = tid & 15;

    u64 acc[4][2] = {};
    for (int k0 = 0; k0 < CDIM; k0 += 16) {
        const int ar = tid >> 2, ac = (tid & 3) * 4;
        float4 a4 = *(const float4*)&W[(size_t)(bm + ar) * CDIM + k0 + ac];
        As[ac + 0][ar] = a4.x; As[ac + 1][ar] = a4.y;
        As[ac + 2][ar] = a4.z; As[ac + 3][ar] = a4.w;
        const int br = tid >> 4, bc = (tid & 15) * 4;
        *(float4*)&Bs[br][bc] = *(const float4*)&Xb[(size_t)(k0 + br) * Ncol + bn + bc];
        __syncthreads();
        #pragma unroll
        for (int kk = 0; kk < 16; ++kk) {
            float4 av = *(const float4*)&As[kk][tm * 4];
            ulonglong2 bv = *(const ulonglong2*)&Bs[kk][tn * 4];
            u64 a0 = pack2(av.x, av.x), a1 = pack2(av.y, av.y);
            u64 a2 = pack2(av.z, av.z), a3 = pack2(av.w, av.w);
            acc[0][0] = fma2(a0, bv.x, acc[0][0]); acc[0][1] = fma2(a0, bv.y, acc[0][1]);
            acc[1][0] = fma2(a1, bv.x, acc[1][0]); acc[1][1] = fma2(a1, bv.y, acc[1][1]);
            acc[2][0] = fma2(a2, bv.x, acc[2][0]); acc[2][1] = fma2(a2, bv.y, acc[2][1]);
            acc[3][0] = fma2(a3, bv.x, acc[3][0]); acc[3][1] = fma2(a3, bv.y, acc[3][1]);
        }
        __syncthreads();
    }
    const int o0 = bm + tm * 4;        // 4 consecutive o (same head), multiple of 4
    const int d0 = o0 & 31;
    const int bh = b * NHEADS + (o0 >> 5);
    #pragma unroll
    for (int j = 0; j < 4; ++j) {
        const int col = bn + tn * 4 + j;
        float vs[4];
        #pragma unroll
        for (int i = 0; i < 4; ++i) {
            float2 f = unpack2(acc[i][j >> 1]);
            vs[i] = (j & 1) ? f.y : f.x;
        }
        u16* base = Out + ((size_t)bh * Ncol + col) * 32 + d0;
        *(u64*)base = cvt4h(make_float4(vs[0], vs[1], vs[2], vs[3]));
    }
}

// ---------------- alpha/bias --------------------------------------------------
__global__ __launch_bounds__(256) void alpha_kernel(
    const float* __restrict__ wproj, const float* __restrict__ v,
    const float* __restrict__ gam, const float* __restrict__ bet,
    const float* __restrict__ mu,  const float* __restrict__ var,
    float* __restrict__ alpha, float* __restrict__ bias) {
    const int b = blockIdx.x;
    const int o = threadIdx.x;
    __shared__ float vs[CDIM];
    vs[o] = v[b * CDIM + o];
    __syncthreads();
    float p = 0.f;
    const float* wr = wproj + (size_t)o * CDIM;
    #pragma unroll 8
    for (int c = 0; c < CDIM; ++c) p = fmaf(wr[c], vs[c], p);
    const float inv = gam[o] * rsqrtf(var[o] + EPSBN);
    alpha[b * CDIM + o] = p * inv;
    if (b == 0) bias[o] = bet[o] - mu[o] * inv;
}

// ===================== fp16 mma.sync attention (kv-split) =====================
// grid (seg 8, half 2, bh 16); 256 threads; smem = k 32KB + q 8KB = 40KB.
// Rows are 64B (32 fp16), packed 2 per 128B swizzled line.
#define SM_QOFF 32768
#define SM_TOT  40960
#define NTILES  16

__global__ __launch_bounds__(256, 2)
void attn_mma(const u16* __restrict__ qbf, const u16* __restrict__ kbf,
              float* __restrict__ attn) {
    extern __shared__ char smem[];
    const u32 sb  = smem_u32(smem);
    const int tid = threadIdx.x;
    const int wid = tid >> 5, l = tid & 31;
    const int seg  = blockIdx.x;
    const int half = blockIdx.y;
    const int bh   = blockIdx.z;

    // stage this half's k (512 rows x 64B)
    {
        const uint4* ksrc = (const uint4*)(kbf + (size_t)(bh * NKV + half * 512) * 32);
        for (int idx = tid; idx < 512 * 4; idx += 256) {
            const int row = idx >> 2, c = idx & 3;
            const u32 off = (u32)((row >> 1) * 128 + (row & 1) * 64 + c * 16);
            *(uint4*)(smem + sw128(off)) = ksrc[idx];
        }
    }
    __syncthreads();

    // B frag lane addresses (kv rows in 16-groups, d chunks)
    const int brow = (l & 7) + ((l & 16) >> 1);
    u32 baddr[2];
    #pragma unroll
    for (int s = 0; s < 2; ++s) {
        const u32 off = (u32)((brow >> 1) * 128 + (brow & 1) * 64
                              + (2 * s + ((l >> 3) & 1)) * 16);
        baddr[s] = sb + sw128(off);
    }
    // A frag lane addresses (this warp's 16 q rows)
    const int Rr = wid * 16 + (l & 15);
    u32 aaddr[2];
    #pragma unroll
    for (int s = 0; s < 2; ++s) {
        const u32 off = (u32)((Rr >> 1) * 128 + (Rr & 1) * 64 + (2 * s + (l >> 4)) * 16);
        aaddr[s] = sb + SM_QOFF + sw128(off);
    }

    const float scale = 0.17677669529663687f;
    float* ob = attn + ((size_t)(half * 16 + bh)) * NDIM;

    for (int t = 0; t < NTILES; ++t) {
        const int n_base = (seg * NTILES + t) * 128;
        // q tile store: thread t -> row t>>1 (warp-local rows only)
        {
            const uint4* qsrc = (const uint4*)(qbf + ((size_t)bh * NDIM + n_base) * 32);
            const int row = tid >> 1;
            const int c0 = (tid & 1) * 2;
            #pragma unroll
            for (int j = 0; j < 2; ++j) {
                const int c = c0 + j;
                const u32 off = (u32)((row >> 1) * 128 + (row & 1) * 64 + c * 16);
                *(uint4*)(smem + SM_QOFF + sw128(off)) = qsrc[(size_t)row * 4 + c];
            }
        }
        __syncwarp();

        u32 a[2][4];
        ldm_x4(a[0], aaddr[0]);
        ldm_x4(a[1], aaddr[1]);
        __syncwarp();

        float rmax[2] = {-INFINITY, -INFINITY};
        for (int kv = 0; kv < 32; ++kv) {
            const u32 off = (u32)kv * 1024;
            u32 b0[4], b1[4];
            ldm_x4(b0, baddr[0] + off);   // d0-15, groups g0/g1
            ldm_x4(b1, baddr[1] + off);   // d16-31
            #pragma unroll
            for (int g = 0; g < 2; ++g) {
                float A0, A1, A2, A3, B0, B1, B2, B3;
                mma_z(A0, A1, A2, A3, a[0][0], a[0][1], a[0][2], a[0][3],
                      b0[2 * g], b0[2 * g + 1]);
                mma_z(B0, B1, B2, B3, a[1][0], a[1][1], a[1][2], a[1][3],
                      b1[2 * g], b1[2 * g + 1]);
                rmax[0] = fmaxf(rmax[0], fmaxf(A0 + B0, A1 + B1));
                rmax[1] = fmaxf(rmax[1], fmaxf(A2 + B2, A3 + B3));
            }
        }
        #pragma unroll
        for (int rr = 0; rr < 2; ++rr) {
            float v = rmax[rr];
            v = fmaxf(v, __shfl_xor_sync(0xffffffffu, v, 1));
            v = fmaxf(v, __shfl_xor_sync(0xffffffffu, v, 2));
            rmax[rr] = v;
        }
        if ((l & 3) == 0) {
            const int rbase = n_base + wid * 16;
            ob[rbase + (l >> 2) + 0] = rmax[0] * scale;
            ob[rbase + (l >> 2) + 8] = rmax[1] * scale;
        }
        __syncwarp();
    }
}

// ---------------- S[b][n] = sum_h max(half0, half1) ---------------------------
__global__ __launch_bounds__(256) void reduce_attn(const float* __restrict__ attn,
                                                   float* __restrict__ S) {
    const int idx = blockIdx.x * 256 + threadIdx.x;
    const int b = idx >> 14, n = idx & (NDIM - 1);
    float s = 0.f;
    #pragma unroll
    for (int h = 0; h < NHEADS; ++h) {
        const size_t base = ((size_t)(b * NHEADS + h)) * NDIM + n;
        s += fmaxf(attn[base], attn[base + (size_t)16 * NDIM]);
    }
    S[idx] = s;
}

// ---------------- out = alpha*S + bias -----------------------------------------
__global__ __launch_bounds__(256) void final_kernel(
    const float* __restrict__ S, const float* __restrict__ alpha,
    const float* __restrict__ bias, float* __restrict__ out) {
    const size_t t = (size_t)blockIdx.x * 256 + threadIdx.x;
    const size_t idx4 = t * 4;
    const int bo = (int)(idx4 >> 14);
    const int n  = (int)(idx4 & (NDIM - 1));
    const int b  = bo >> 8, o = bo & 255;
    const float a  = alpha[bo];
    const float bi = bias[o];
    float4 s = *(const float4*)&S[(size_t)b * NDIM + n];
    float4 r;
    r.x = fmaf(a, s.x, bi); r.y = fmaf(a, s.y, bi);
    r.z = fmaf(a, s.z, bi); r.w = fmaf(a, s.w, bi);
    *(float4*)&out[idx4] = r;
}

// ===================== launch ==================================================
extern "C" void kernel_launch(void* const* d_in, const int* in_sizes, int n_in,
                              void* d_out, int out_size) {
    const float* x      = (const float*)d_in[0];
    const float* w_q    = (const float*)d_in[1];
    const float* w_k    = (const float*)d_in[2];
    const float* w_sr   = (const float*)d_in[3];
    const float* sr_g   = (const float*)d_in[4];
    const float* sr_b   = (const float*)d_in[5];
    const float* sr_m   = (const float*)d_in[6];
    const float* sr_v   = (const float*)d_in[7];
    const float* w_proj = (const float*)d_in[8];
    const float* pj_g   = (const float*)d_in[9];
    const float* pj_b   = (const float*)d_in[10];
    const float* pj_m   = (const float*)d_in[11];
    const float* pj_v   = (const float*)d_in[12];
    float* out = (float*)d_out;

    u16 *qbf, *kbf, *Xt, *Xp, *wqs, *wsrs;
    float *part, *xr, *attn, *S, *vp, *v, *alpha, *bias;
    cudaGetSymbolAddress((void**)&qbf,   g_qbf);
    cudaGetSymbolAddress((void**)&kbf,   g_kbf);
    cudaGetSymbolAddress((void**)&Xt,    g_Xt);
    cudaGetSymbolAddress((void**)&Xp,    g_Xp);
    cudaGetSymbolAddress((void**)&wqs,   g_wqs);
    cudaGetSymbolAddress((void**)&wsrs,  g_wsrs);
    cudaGetSymbolAddress((void**)&part,  g_part);
    cudaGetSymbolAddress((void**)&xr,    g_xr);
    cudaGetSymbolAddress((void**)&attn,  g_attn);
    cudaGetSymbolAddress((void**)&S,     g_S);
    cudaGetSymbolAddress((void**)&vp,    g_vp);
    cudaGetSymbolAddress((void**)&v,     g_v);
    cudaGetSymbolAddress((void**)&alpha, g_alpha);
    cudaGetSymbolAddress((void**)&bias,  g_bias);

    cudaFuncSetAttribute(attn_mma, cudaFuncAttributeMaxDynamicSharedMemorySize, SM_TOT);
    cudaFuncSetAttribute(qgemm_mma, cudaFuncAttributeMaxDynamicSharedMemorySize, 49152);
    cudaFuncSetAttribute(convgemm_mma, cudaFuncAttributeMaxDynamicSharedMemorySize, 49152);
    cudaFuncSetAttribute(gather_patches, cudaFuncAttributeMaxDynamicSharedMemorySize, 32768);

    // prep
    convert_w<<<64, 256>>>(w_q, wqs, 256);
    convert_w<<<1024, 256>>>(w_sr, wsrs, 4096);
    transpose_split_x<<<dim3(256, 4, 2), 256>>>(x, Xt, vp);
    gather_patches<<<dim3(8, 32, 2), 256, 32768>>>(x, Xp);
    // q = w_q @ x  (fp16 tensor cores)
    qgemm_mma<<<dim3(128, 2, 2), 256, 49152>>>(Xt, wqs, qbf);
    // xr = BN(conv_sr(x))  (fp16 tensor cores, split-K)
    convgemm_mma<<<dim3(8, 2, 16), 256, 49152>>>(wsrs, Xp, part);
    conv_reduce_bn<<<512, 256>>>(part, sr_g, sr_b, sr_m, sr_v, xr);
    // k = w_k @ xr (scalar, small)
    gemm_split<<<dim3(NKV / 64, CDIM / 64, BSZ), 256>>>(w_k, xr, kbf, NKV);
    // v, alpha
    vp_reduce<<<BSZ * CDIM, 256>>>(vp, v);
    alpha_kernel<<<BSZ, CDIM>>>(w_proj, v, pj_g, pj_b, pj_m, pj_v, alpha, bias);
    // attention rowmax (fp16 tensor cores)
    attn_mma<<<dim3(8, 2, 16), 256, SM_TOT>>>(qbf, kbf, attn);
    // tail
    reduce_attn<<<BSZ * NDIM / 256, 256>>>(attn, S);
    final_kernel<<<(BSZ * CDIM * NDIM / 4) / 256, 256>>>(S, alpha, bias, out);
}